// round 5
// baseline (speedup 1.0000x reference)
#include <cuda_runtime.h>
#include <math.h>

#define H      1024
#define SLEN   128
#define VOCAB  32000
#define STEPS  51
#define EOS_ID 2
#define GRID   512
#define TPB    256
#define NWARP  8
#define NLOGB  500                  // blocks [0..499] = logits partition
#define LOGW   (NLOGB * NWARP)      // 4000 warps -> exactly 8 rows each
#define SIDE0  NLOGB                // blocks [500..511] = side partition
#define NSIDE  12
#define NSW    (NSIDE * NWARP)      // 96 side warps

// ---------------- persistent device state ----------------
__device__ float g_hbuf[2][H];
__device__ float g_c[H];
__device__ float g_hs[SLEN * H];
__device__ float g_scores[SLEN];
__device__ float g_d[H];
__device__ float g_ht2[2][H];       // projected attention vector, double-buffered
__device__ float g_pval[2][NLOGB];
__device__ int   g_pidx[2][NLOGB];
__device__ int   g_wid;
__device__ int   g_done;
__device__ unsigned int g_bar_count;
__device__ unsigned int g_bar2;

__global__ void k_init() {
    int t = threadIdx.x;            // 1024 threads
    g_hbuf[0][t] = 0.f;
    g_c[t] = 0.f;
    if (t == 0) { g_done = 0; g_bar_count = 0u; g_bar2 = 0u; }
}

// ---------------- barriers ----------------
__device__ __forceinline__ void gbar(unsigned int& gen) {
    __syncthreads();
    gen += GRID;
    if (threadIdx.x == 0) {
        asm volatile("fence.acq_rel.gpu;" ::: "memory");
        unsigned int prev = atomicAdd(&g_bar_count, 1u);
        if (prev + 1u != gen) {
            while (*(volatile unsigned int*)&g_bar_count < gen) { }
        }
        asm volatile("fence.acq_rel.gpu;" ::: "memory");
    }
    __syncthreads();
}

__device__ __forceinline__ void sbar(unsigned int& gen2) {   // side blocks only
    __syncthreads();
    gen2 += NSIDE;
    if (threadIdx.x == 0) {
        asm volatile("fence.acq_rel.gpu;" ::: "memory");
        unsigned int prev = atomicAdd(&g_bar2, 1u);
        if (prev + 1u != gen2) {
            while (*(volatile unsigned int*)&g_bar2 < gen2) { }
        }
        asm volatile("fence.acq_rel.gpu;" ::: "memory");
    }
    __syncthreads();
}

__device__ __forceinline__ float sigf(float x) { return 1.f / (1.f + expf(-x)); }
__device__ __forceinline__ float dp4(float4 a, float4 b) {
    return a.x * b.x + a.y * b.y + a.z * b.z + a.w * b.w;
}
__device__ __forceinline__ float wred(float v) {
#pragma unroll
    for (int o = 16; o; o >>= 1) v += __shfl_down_sync(0xffffffffu, v, o);
    return v;
}

// ---------------- LSTM pieces: grid-wide, block b owns units 2b,2b+1; warp = one gate row --------
__device__ __forceinline__ void lstm_whh(const float* __restrict__ Whh,
                                         const float* __restrict__ hprev, float* s_g)
{
    const int b = blockIdx.x, w = threadIdx.x >> 5, lane = threadIdx.x & 31;
    const int j = b * 2 + (w >> 2), g = w & 3;
    const float4* wh = (const float4*)(Whh + (size_t)(g * H + j) * H);
    const float4* h4 = (const float4*)hprev;
    float acc = 0.f;
#pragma unroll
    for (int i = 0; i < 8; i++) acc += dp4(wh[lane + 32 * i], h4[lane + 32 * i]);
    acc = wred(acc);
    if (!lane) s_g[w] = acc;
}

__device__ __forceinline__ void lstm_pointwise(const float* __restrict__ bih,
                                               const float* __restrict__ bhh,
                                               float* __restrict__ hnext,
                                               float* __restrict__ hs_out, float* s_g)
{
    __syncthreads();
    if (threadIdx.x < 2) {
        const int j = blockIdx.x * 2 + threadIdx.x;
        const int base = threadIdx.x * 4;
        float gi = s_g[base + 0] + bih[j]         + bhh[j];
        float gf = s_g[base + 1] + bih[H + j]     + bhh[H + j];
        float gg = s_g[base + 2] + bih[2 * H + j] + bhh[2 * H + j];
        float go = s_g[base + 3] + bih[3 * H + j] + bhh[3 * H + j];
        float i_ = sigf(gi), f_ = sigf(gf), g_ = tanhf(gg), o_ = sigf(go);
        float c2 = f_ * g_c[j] + i_ * g_;
        g_c[j] = c2;
        float hn = o_ * tanhf(c2);
        hnext[j] = hn;
        if (hs_out) hs_out[j] = hn;
    }
}

__device__ __forceinline__ void lstm_wih_pw(const float* __restrict__ Wih,
                                            const float* __restrict__ xrow,
                                            const float* __restrict__ bih,
                                            const float* __restrict__ bhh,
                                            float* __restrict__ hnext,
                                            float* __restrict__ hs_out, float* s_g)
{
    const int b = blockIdx.x, w = threadIdx.x >> 5, lane = threadIdx.x & 31;
    const int j = b * 2 + (w >> 2), g = w & 3;
    const float4* wi = (const float4*)(Wih + (size_t)(g * H + j) * H);
    const float4* x4 = (const float4*)xrow;
    float acc = 0.f;
#pragma unroll
    for (int i = 0; i < 8; i++) acc += dp4(wi[lane + 32 * i], x4[lane + 32 * i]);
    acc = wred(acc);
    if (!lane) s_g[w] += acc;
    lstm_pointwise(bih, bhh, hnext, hs_out, s_g);
}

__device__ __forceinline__ void lstm_full(const float* __restrict__ Wih,
                                          const float* __restrict__ Whh,
                                          const float* __restrict__ bih,
                                          const float* __restrict__ bhh,
                                          const float* __restrict__ xrow,
                                          const float* __restrict__ hprev,
                                          float* __restrict__ hnext,
                                          float* __restrict__ hs_out, float* s_g)
{
    const int b = blockIdx.x, w = threadIdx.x >> 5, lane = threadIdx.x & 31;
    const int j = b * 2 + (w >> 2), g = w & 3;
    const float4* wi = (const float4*)(Wih + (size_t)(g * H + j) * H);
    const float4* wh = (const float4*)(Whh + (size_t)(g * H + j) * H);
    const float4* x4 = (const float4*)xrow;
    const float4* h4 = (const float4*)hprev;
    float acc = 0.f;
#pragma unroll
    for (int i = 0; i < 8; i++) acc += dp4(wi[lane + 32 * i], x4[lane + 32 * i]);
#pragma unroll
    for (int i = 0; i < 8; i++) acc += dp4(wh[lane + 32 * i], h4[lane + 32 * i]);
    acc = wred(acc);
    if (!lane) s_g[w] = acc;
    lstm_pointwise(bih, bhh, hnext, hs_out, s_g);
}

// ---------------- attention scores: one warp per source row ----------------
__device__ __forceinline__ void scores_row(int s, const float* __restrict__ ht)
{
    if (s >= SLEN) return;
    const int lane = threadIdx.x & 31;
    const float4* r  = (const float4*)(g_hs + (size_t)s * H);
    const float4* h4 = (const float4*)ht;
    float acc = 0.f;
#pragma unroll
    for (int i = 0; i < 8; i++) acc += dp4(r[lane + 32 * i], h4[lane + 32 * i]);
    acc = wred(acc);
    if (!lane) g_scores[s] = acc;
}

// ---------------- softmax + context: 4 cooperating blocks (bsel 0..3) ----------------
__device__ __forceinline__ void context_piece(int bsel, float* s_sc, float* s_a, float* s_scalar)
{
    if (bsel < 0 || bsel >= 4) return;
    const int tid = threadIdx.x, w = tid >> 5, lane = tid & 31;
    if (tid < SLEN) s_sc[tid] = g_scores[tid];
    __syncthreads();
    if (w == 0) {
        float m = -INFINITY;
#pragma unroll
        for (int q = 0; q < 4; q++) m = fmaxf(m, s_sc[lane + 32 * q]);
#pragma unroll
        for (int o = 16; o; o >>= 1) m = fmaxf(m, __shfl_xor_sync(0xffffffffu, m, o));
        float sum = 0.f;
#pragma unroll
        for (int q = 0; q < 4; q++) {
            float e = expf(s_sc[lane + 32 * q] - m);
            s_a[lane + 32 * q] = e;
            sum += e;
        }
#pragma unroll
        for (int o = 16; o; o >>= 1) sum += __shfl_xor_sync(0xffffffffu, sum, o);
        if (!lane) s_scalar[0] = 1.f / sum;
    }
    __syncthreads();
    const float inv = s_scalar[0];
    const int j = bsel * TPB + tid;
    float acc = 0.f;
#pragma unroll 8
    for (int s = 0; s < SLEN; s++) acc += s_a[s] * g_hs[(size_t)s * H + j];
    g_d[j] = acc * inv;
}

// ---------------- proj row: ht2[r] = tanh(Wtl[r] @ [d;ht] + b[r]) ----------------
__device__ __forceinline__ void proj_row(int r, const float* __restrict__ Wtl,
                                         const float* __restrict__ btl,
                                         const float* __restrict__ ht,
                                         float* __restrict__ ht2out)
{
    if (r >= H) return;
    const int lane = threadIdx.x & 31;
    const float4* wr = (const float4*)(Wtl + (size_t)r * 2 * H);
    const float4* d4 = (const float4*)g_d;
    const float4* h4 = (const float4*)ht;
    float acc = 0.f;
#pragma unroll
    for (int i = 0; i < 8; i++) acc += dp4(wr[lane + 32 * i], d4[lane + 32 * i]);
#pragma unroll
    for (int i = 0; i < 8; i++) acc += dp4(wr[256 + lane + 32 * i], h4[lane + 32 * i]);
    acc = wred(acc);
    if (!lane) ht2out[r] = tanhf(acc + btl[r]);
}

// ---------------- logits GEMV: blocks 0..499, exactly 8 rows/warp as 4 row-pairs ----------------
__device__ __forceinline__ void logits_main(const float* __restrict__ W,
                                            const float* __restrict__ bias,
                                            const float* __restrict__ vec,
                                            float* __restrict__ out_logits,
                                            int slot, float* s_v, int* s_i, float4* s_x)
{
    const int tid = threadIdx.x, w = tid >> 5, lane = tid & 31;
    // stage vec in shared (frees regs for row-pair staging)
    s_x[tid] = ((const float4*)vec)[tid];
    __syncthreads();

    const int gw = blockIdx.x * NWARP + w;          // 0..3999
    float best = -INFINITY; int bidx = VOCAB;
#pragma unroll
    for (int p = 0; p < 4; p++) {
        const int r0 = gw + LOGW * (2 * p);         // ascending across p
        const int r1 = r0 + LOGW;
        const float4* w0 = (const float4*)(W + (size_t)r0 * H);
        const float4* w1 = (const float4*)(W + (size_t)r1 * H);
        float acc0 = 0.f, acc1 = 0.f;
#pragma unroll
        for (int q = 0; q < 8; q++) {
            const int k = lane + 32 * q;
            float4 a = __ldcs(w0 + k);
            float4 b = __ldcs(w1 + k);
            float4 x = s_x[k];
            acc0 += dp4(a, x);
            acc1 += dp4(b, x);
        }
        acc0 = wred(acc0);
        acc1 = wred(acc1);
        if (!lane) {
            float l0 = acc0 + bias[r0];
            float l1 = acc1 + bias[r1];
            if (out_logits) { __stcs(out_logits + r0, l0); __stcs(out_logits + r1, l1); }
            if (l0 > best) { best = l0; bidx = r0; }
            if (l1 > best) { best = l1; bidx = r1; }
        }
    }
    if (!lane) { s_v[w] = best; s_i[w] = bidx; }
    __syncthreads();
    if (tid == 0) {
        float bv = s_v[0]; int bi = s_i[0];
#pragma unroll
        for (int q = 1; q < NWARP; q++)
            if (s_v[q] > bv || (s_v[q] == bv && s_i[q] < bi)) { bv = s_v[q]; bi = s_i[q]; }
        g_pval[slot][blockIdx.x] = bv; g_pidx[slot][blockIdx.x] = bi;
    }
}

// ---------------- final argmax + token emit ----------------
__device__ __forceinline__ void finalize_piece(int step, int slot, float* __restrict__ out_toks,
                                               float* s_v, int* s_i)
{
    const int t = threadIdx.x;
    float bv = -INFINITY; int bi = VOCAB;
    for (int p = t; p < NLOGB; p += TPB) {
        float v = g_pval[slot][p]; int i = g_pidx[slot][p];
        if (v > bv || (v == bv && i < bi)) { bv = v; bi = i; }
    }
    s_v[t] = bv; s_i[t] = bi;
    __syncthreads();
    for (int st = 128; st > 0; st >>= 1) {
        if (t < st) {
            float v = s_v[t + st]; int i = s_i[t + st];
            if (v > s_v[t] || (v == s_v[t] && i < s_i[t])) { s_v[t] = v; s_i[t] = i; }
        }
        __syncthreads();
    }
    if (t == 0) {
        int wid = s_i[0];
        int done_prev = (step >= 0) ? g_done : 0;
        int is_eos = (wid == EOS_ID);
        if (step >= 0) out_toks[step] = (float)((done_prev || is_eos) ? -1 : wid);
        g_wid = wid;
        g_done = done_prev | is_eos;
    }
    __syncthreads();
}

// ---------------- the whole model, one persistent kernel ----------------
__global__ void __launch_bounds__(TPB, 4) k_main(
    const int* __restrict__ src,
    const float* __restrict__ embI,
    const float* __restrict__ WihE, const float* __restrict__ WhhE,
    const float* __restrict__ bihE, const float* __restrict__ bhhE,
    const float* __restrict__ Wli,  const float* __restrict__ bli,
    const float* __restrict__ embT,
    const float* __restrict__ WihD, const float* __restrict__ WhhD,
    const float* __restrict__ bihD, const float* __restrict__ bhhD,
    const float* __restrict__ Wlt,  const float* __restrict__ blt,
    const float* __restrict__ Wtl,  const float* __restrict__ btl,
    float* __restrict__ out)
{
    __shared__ float  s_g[8];       // LSTM gate partials; persists across P1->P2 grid barrier
    __shared__ float  s_v[256];
    __shared__ int    s_i[256];
    __shared__ float  s_sc[SLEN];
    __shared__ float  s_a[SLEN];
    __shared__ float  s_scalar[1];
    __shared__ float4 s_x[256];     // staged logits input vector

    unsigned int gen = 0, gen2 = 0;
    float* out_logits = out + STEPS;
    const int b = blockIdx.x;
    const int w = threadIdx.x >> 5;

    // ---- encoder: 128 sequential full-LSTM phases (grid-wide) ----
    for (int t = 0; t < SLEN; t++) {
        lstm_full(WihE, WhhE, bihE, bhhE, embI + (size_t)src[t] * H,
                  g_hbuf[t & 1], g_hbuf[(t + 1) & 1], g_hs + (size_t)t * H, s_g);
        gbar(gen);
    }
    // final encoder h in g_hbuf[0], c in g_c

    // ---- wid0 from final encoder state ----
    if (b < NLOGB) logits_main(Wli, bli, g_hbuf[0], nullptr, 1, s_v, s_i, s_x);
    gbar(gen);
    if (b == 4) finalize_piece(-1, 1, out, s_v, s_i);        // g_wid = wid0
    gbar(gen);

    // ---- initial decoder LSTM: ht(0) -> g_hbuf[1] ----
    lstm_full(WihD, WhhD, bihD, bhhD, embT + (size_t)g_wid * H,
              g_hbuf[0], g_hbuf[1], nullptr, s_g);
    gbar(gen);

    // ---- prologue: scores(0), context(0), proj(0) -> ht2[0] (grid-wide) ----
    if (b < 16) scores_row(b * NWARP + w, g_hbuf[1]);
    gbar(gen);
    context_piece(b < 4 ? b : -1, s_sc, s_a, s_scalar);
    gbar(gen);
    if (b < 128) proj_row(b * NWARP + w, Wtl, btl, g_hbuf[1], g_ht2[0]);
    gbar(gen);

    // ---- decode loop: 3 grid barriers/step; attention tail hidden under logits ----
    int cur = 1;                                    // ht(t) = g_hbuf[cur]
    for (int t = 0; t < STEPS; t++) {
        const float* ht  = g_hbuf[cur];
        float*       htn = g_hbuf[1 - cur];

        // P1: Whh half (grid-wide) || finalize(t-1) on block 4
        lstm_whh(WhhD, ht, s_g);
        if (t > 0 && b == 4) finalize_piece(t - 1, (t - 1) & 1, out, s_v, s_i);
        gbar(gen);

        // P2: Wih half + pointwise -> ht(t+1) (grid-wide; uses wid_{t-1})
        lstm_wih_pw(WihD, embT + (size_t)g_wid * H, bihD, bhhD, htn, nullptr, s_g);
        gbar(gen);

        // P3: logits(t) on blocks 0..499 || attention tail for step t+1 on blocks 500..511
        if (b < NLOGB) {
            logits_main(Wlt, blt, g_ht2[t & 1], out_logits + (size_t)t * VOCAB,
                        t & 1, s_v, s_i, s_x);
        } else {
            const int g = (b - SIDE0) * NWARP + w;  // 0..95
            scores_row(g, htn);
            scores_row(g + NSW, htn);
            sbar(gen2);
            context_piece(b - SIDE0 < 4 ? b - SIDE0 : -1, s_sc, s_a, s_scalar);
            sbar(gen2);
#pragma unroll
            for (int k = 0; k < 11; k++) proj_row(g + NSW * k, Wtl, btl, htn, g_ht2[(t + 1) & 1]);
        }
        gbar(gen);
        cur ^= 1;
    }
    if (b == 4) finalize_piece(STEPS - 1, (STEPS - 1) & 1, out, s_v, s_i);
}

// ---------------- host orchestration ----------------
extern "C" void kernel_launch(void* const* d_in, const int* in_sizes, int n_in,
                              void* d_out, int out_size)
{
    const int*   src  = (const int*)  d_in[0];
    const float* embI = (const float*)d_in[1];
    const float* WihE = (const float*)d_in[2];
    const float* WhhE = (const float*)d_in[3];
    const float* bihE = (const float*)d_in[4];
    const float* bhhE = (const float*)d_in[5];
    const float* Wli  = (const float*)d_in[6];
    const float* bli  = (const float*)d_in[7];
    const float* embT = (const float*)d_in[8];
    const float* WihD = (const float*)d_in[9];
    const float* WhhD = (const float*)d_in[10];
    const float* bihD = (const float*)d_in[11];
    const float* bhhD = (const float*)d_in[12];
    const float* Wlt  = (const float*)d_in[13];
    const float* blt  = (const float*)d_in[14];
    const float* Wtl  = (const float*)d_in[15];
    const float* btl  = (const float*)d_in[16];

    k_init<<<1, 1024>>>();
    k_main<<<GRID, TPB>>>(src, embI, WihE, WhhE, bihE, bhhE, Wli, bli, embT,
                          WihD, WhhD, bihD, bhhD, Wlt, blt, Wtl, btl,
                          (float*)d_out);
}

// round 6
// speedup vs baseline: 1.1805x; 1.1805x over previous
#include <cuda_runtime.h>
#include <math.h>

#define H      1024
#define SLEN   128
#define VOCAB  32000
#define STEPS  51
#define EOS_ID 2
#define GRID   512
#define TPB    256
#define NWARP  8
#define NLOGB  500                  // blocks [0..499] do logits: 4000 warps x 8 contiguous rows
#define SIDE0  NLOGB                // blocks [500..511] do attention scores in P3
#define NSW    ((GRID - NLOGB) * NWARP)   // 96 score warps

// ---------------- persistent device state ----------------
__device__ float g_hbuf[2][H];
__device__ float g_c[H];
__device__ float g_hs[SLEN * H];
__device__ float g_scores[SLEN];
__device__ float g_d[H];
__device__ float g_htnew[H];
__device__ float g_pval[NLOGB];
__device__ int   g_pidx[NLOGB];
__device__ int   g_wid;
__device__ int   g_done;
__device__ unsigned int g_bar_count;

__global__ void k_init() {
    int t = threadIdx.x;             // 1024 threads
    g_hbuf[0][t] = 0.f;
    g_c[t] = 0.f;
    if (t == 0) { g_done = 0; g_bar_count = 0u; }
}

// ---------------- grid barrier: 1-thread arrival, acq_rel fences, monotonic count ----------------
__device__ __forceinline__ void gbar(unsigned int& gen) {
    __syncthreads();
    gen += GRID;
    if (threadIdx.x == 0) {
        asm volatile("fence.acq_rel.gpu;" ::: "memory");
        unsigned int prev = atomicAdd(&g_bar_count, 1u);
        if (prev + 1u != gen) {
            while (*(volatile unsigned int*)&g_bar_count < gen) { }
        }
        asm volatile("fence.acq_rel.gpu;" ::: "memory");
    }
    __syncthreads();
}

__device__ __forceinline__ float sigf(float x) { return 1.f / (1.f + expf(-x)); }
__device__ __forceinline__ float dp4(float4 a, float4 b) {
    return a.x * b.x + a.y * b.y + a.z * b.z + a.w * b.w;
}
__device__ __forceinline__ float wred(float v) {
#pragma unroll
    for (int o = 16; o; o >>= 1) v += __shfl_down_sync(0xffffffffu, v, o);
    return v;
}

// ---------------- LSTM pieces (blocks 0..511, unit j = b*2 + w/4, gate = w%4) ----------------
__device__ __forceinline__ void lstm_whh(const float* __restrict__ Whh,
                                         const float* __restrict__ hprev, float* s_g)
{
    const int b = blockIdx.x, w = threadIdx.x >> 5, lane = threadIdx.x & 31;
    const int j = b * 2 + (w >> 2), g = w & 3;
    const float4* wh = (const float4*)(Whh + (size_t)(g * H + j) * H);
    const float4* h4 = (const float4*)hprev;
    float acc = 0.f;
#pragma unroll
    for (int i = 0; i < 8; i++) acc += dp4(wh[lane + 32 * i], h4[lane + 32 * i]);
    acc = wred(acc);
    if (!lane) s_g[w] = acc;
}

__device__ __forceinline__ void lstm_pointwise(const float* __restrict__ bih,
                                               const float* __restrict__ bhh,
                                               float* __restrict__ hnext,
                                               float* __restrict__ hs_out, float* s_g)
{
    __syncthreads();
    const int tid = threadIdx.x;
    if (tid < 2) {
        const int j = blockIdx.x * 2 + tid;
        const int base = tid * 4;
        float gi = s_g[base + 0] + bih[j]         + bhh[j];
        float gf = s_g[base + 1] + bih[H + j]     + bhh[H + j];
        float gg = s_g[base + 2] + bih[2 * H + j] + bhh[2 * H + j];
        float go = s_g[base + 3] + bih[3 * H + j] + bhh[3 * H + j];
        float i_ = sigf(gi), f_ = sigf(gf), g_ = tanhf(gg), o_ = sigf(go);
        float c2 = f_ * g_c[j] + i_ * g_;
        g_c[j] = c2;
        float hn = o_ * tanhf(c2);
        hnext[j] = hn;
        if (hs_out) hs_out[j] = hn;
    }
}

// Wih half: adds x-dot into s_g, then pointwise
__device__ __forceinline__ void lstm_wih_pw(const float* __restrict__ Wih,
                                            const float* __restrict__ xrow,
                                            const float* __restrict__ bih,
                                            const float* __restrict__ bhh,
                                            float* __restrict__ hnext,
                                            float* __restrict__ hs_out, float* s_g)
{
    const int b = blockIdx.x, w = threadIdx.x >> 5, lane = threadIdx.x & 31;
    const int j = b * 2 + (w >> 2), g = w & 3;
    const float4* wi = (const float4*)(Wih + (size_t)(g * H + j) * H);
    const float4* x4 = (const float4*)xrow;
    float acc = 0.f;
#pragma unroll
    for (int i = 0; i < 8; i++) acc += dp4(wi[lane + 32 * i], x4[lane + 32 * i]);
    acc = wred(acc);
    if (!lane) s_g[w] += acc;
    lstm_pointwise(bih, bhh, hnext, hs_out, s_g);
}

// full LSTM (encoder / initial decoder step): both halves in one phase
__device__ __forceinline__ void lstm_full(const float* __restrict__ Wih,
                                          const float* __restrict__ Whh,
                                          const float* __restrict__ bih,
                                          const float* __restrict__ bhh,
                                          const float* __restrict__ xrow,
                                          const float* __restrict__ hprev,
                                          float* __restrict__ hnext,
                                          float* __restrict__ hs_out, float* s_g)
{
    const int b = blockIdx.x, w = threadIdx.x >> 5, lane = threadIdx.x & 31;
    const int j = b * 2 + (w >> 2), g = w & 3;
    const float4* wi = (const float4*)(Wih + (size_t)(g * H + j) * H);
    const float4* wh = (const float4*)(Whh + (size_t)(g * H + j) * H);
    const float4* x4 = (const float4*)xrow;
    const float4* h4 = (const float4*)hprev;
    float acc = 0.f;
#pragma unroll
    for (int i = 0; i < 8; i++) acc += dp4(wi[lane + 32 * i], x4[lane + 32 * i]);
#pragma unroll
    for (int i = 0; i < 8; i++) acc += dp4(wh[lane + 32 * i], h4[lane + 32 * i]);
    acc = wred(acc);
    if (!lane) s_g[w] = acc;
    lstm_pointwise(bih, bhh, hnext, hs_out, s_g);
}

// ---------------- attention scores: one warp per source row ----------------
__device__ __forceinline__ void scores_row(int s, const float* __restrict__ ht)
{
    if (s >= SLEN) return;
    const int lane = threadIdx.x & 31;
    const float4* r  = (const float4*)(g_hs + (size_t)s * H);
    const float4* h4 = (const float4*)ht;
    float acc = 0.f;
#pragma unroll
    for (int i = 0; i < 8; i++) acc += dp4(r[lane + 32 * i], h4[lane + 32 * i]);
    acc = wred(acc);
    if (!lane) g_scores[s] = acc;
}

// ---------------- softmax + context: blocks 0..3 ----------------
__device__ __forceinline__ void context_piece(float* s_sc, float* s_a, float* s_scalar)
{
    const int b = blockIdx.x;
    if (b >= 4) return;
    const int tid = threadIdx.x, w = tid >> 5, lane = tid & 31;
    if (tid < SLEN) s_sc[tid] = g_scores[tid];
    __syncthreads();
    if (w == 0) {
        float m = -INFINITY;
#pragma unroll
        for (int q = 0; q < 4; q++) m = fmaxf(m, s_sc[lane + 32 * q]);
#pragma unroll
        for (int o = 16; o; o >>= 1) m = fmaxf(m, __shfl_xor_sync(0xffffffffu, m, o));
        float sum = 0.f;
#pragma unroll
        for (int q = 0; q < 4; q++) {
            float e = expf(s_sc[lane + 32 * q] - m);
            s_a[lane + 32 * q] = e;
            sum += e;
        }
#pragma unroll
        for (int o = 16; o; o >>= 1) sum += __shfl_xor_sync(0xffffffffu, sum, o);
        if (!lane) s_scalar[0] = 1.f / sum;
    }
    __syncthreads();
    const float inv = s_scalar[0];
    const int j = b * TPB + threadIdx.x;
    float acc = 0.f;
#pragma unroll 8
    for (int s = 0; s < SLEN; s++) acc += s_a[s] * g_hs[(size_t)s * H + j];
    g_d[j] = acc * inv;
}

// ---------------- proj: blocks 0..127, warp-per-row ----------------
__device__ __forceinline__ void proj_piece(const float* __restrict__ Wtl,
                                           const float* __restrict__ btl,
                                           const float* __restrict__ ht)
{
    const int b = blockIdx.x;
    if (b >= 128) return;
    const int w = threadIdx.x >> 5, lane = threadIdx.x & 31;
    const int r = b * NWARP + w;                     // 0..1023
    const float4* wr = (const float4*)(Wtl + (size_t)r * 2 * H);
    const float4* d4 = (const float4*)g_d;
    const float4* h4 = (const float4*)ht;
    float acc = 0.f;
#pragma unroll
    for (int i = 0; i < 8; i++) acc += dp4(wr[lane + 32 * i], d4[lane + 32 * i]);
#pragma unroll
    for (int i = 0; i < 8; i++) acc += dp4(wr[256 + lane + 32 * i], h4[lane + 32 * i]);
    acc = wred(acc);
    if (!lane) g_htnew[r] = tanhf(acc + btl[r]);
}

// ---------------- logits GEMV: blocks 0..499, 8 CONTIGUOUS rows per warp ----------------
__device__ __forceinline__ void logits_piece(const float* __restrict__ W,
                                             const float* __restrict__ bias,
                                             const float* __restrict__ vec,
                                             float* __restrict__ out_logits,
                                             float* s_v, int* s_i)
{
    const int tid = threadIdx.x, w = tid >> 5, lane = tid & 31;
    const float4* x4 = (const float4*)vec;
    float4 v[8];
#pragma unroll
    for (int q = 0; q < 8; q++) v[q] = x4[lane + 32 * q];
    const int rbase = (blockIdx.x * NWARP + w) * 8;  // warp owns rows [rbase, rbase+8)
    float best = -INFINITY; int bidx = VOCAB;
#pragma unroll
    for (int i = 0; i < 8; i++) {
        const int r = rbase + i;                     // ascending -> strict > keeps lowest idx
        const float4* wr = (const float4*)(W + (size_t)r * H);
        float acc = 0.f;
#pragma unroll
        for (int q = 0; q < 8; q++) acc += dp4(__ldcs(wr + lane + 32 * q), v[q]);
        acc = wred(acc);
        if (!lane) {
            float lg = acc + bias[r];
            if (out_logits) __stcs(out_logits + r, lg);
            if (lg > best) { best = lg; bidx = r; }
        }
    }
    if (!lane) { s_v[w] = best; s_i[w] = bidx; }
    __syncthreads();
    if (tid == 0) {
        float bv = s_v[0]; int bi = s_i[0];
#pragma unroll
        for (int q = 1; q < NWARP; q++)
            if (s_v[q] > bv || (s_v[q] == bv && s_i[q] < bi)) { bv = s_v[q]; bi = s_i[q]; }
        g_pval[blockIdx.x] = bv; g_pidx[blockIdx.x] = bi;
    }
}

// ---------------- final argmax + token emit (block 4) ----------------
__device__ __forceinline__ void finalize_piece(int step, float* __restrict__ out_toks,
                                               float* s_v, int* s_i)
{
    if (blockIdx.x != 4) return;
    const int t = threadIdx.x;
    float bv = -INFINITY; int bi = VOCAB;
    for (int p = t; p < NLOGB; p += TPB) {
        float v = g_pval[p]; int i = g_pidx[p];
        if (v > bv || (v == bv && i < bi)) { bv = v; bi = i; }
    }
    s_v[t] = bv; s_i[t] = bi;
    __syncthreads();
    for (int st = 128; st > 0; st >>= 1) {
        if (t < st) {
            float v = s_v[t + st]; int i = s_i[t + st];
            if (v > s_v[t] || (v == s_v[t] && i < s_i[t])) { s_v[t] = v; s_i[t] = i; }
        }
        __syncthreads();
    }
    if (t == 0) {
        int wid = s_i[0];
        int done_prev = (step >= 0) ? g_done : 0;
        int is_eos = (wid == EOS_ID);
        if (step >= 0) out_toks[step] = (float)((done_prev || is_eos) ? -1 : wid);
        g_wid = wid;
        g_done = done_prev | is_eos;
    }
    __syncthreads();
}

// ---------------- the whole model, one persistent kernel ----------------
__global__ void __launch_bounds__(TPB, 4) k_main(
    const int* __restrict__ src,
    const float* __restrict__ embI,
    const float* __restrict__ WihE, const float* __restrict__ WhhE,
    const float* __restrict__ bihE, const float* __restrict__ bhhE,
    const float* __restrict__ Wli,  const float* __restrict__ bli,
    const float* __restrict__ embT,
    const float* __restrict__ WihD, const float* __restrict__ WhhD,
    const float* __restrict__ bihD, const float* __restrict__ bhhD,
    const float* __restrict__ Wlt,  const float* __restrict__ blt,
    const float* __restrict__ Wtl,  const float* __restrict__ btl,
    float* __restrict__ out)
{
    __shared__ float s_g[8];         // gate partials; PERSISTS across the P1->P2 grid barrier
    __shared__ float s_v[256];
    __shared__ int   s_i[256];
    __shared__ float s_sc[SLEN];
    __shared__ float s_a[SLEN];
    __shared__ float s_scalar[1];

    unsigned int gen = 0;
    float* out_logits = out + STEPS;
    const int b = blockIdx.x;
    const int w = threadIdx.x >> 5;

    // ---- encoder: 128 sequential full-LSTM phases ----
    for (int t = 0; t < SLEN; t++) {
        lstm_full(WihE, WhhE, bihE, bhhE, embI + (size_t)src[t] * H,
                  g_hbuf[t & 1], g_hbuf[(t + 1) & 1], g_hs + (size_t)t * H, s_g);
        gbar(gen);
    }
    // final encoder h in g_hbuf[0], c in g_c

    // ---- first word ----
    if (b < NLOGB) logits_piece(Wli, bli, g_hbuf[0], nullptr, s_v, s_i);
    gbar(gen);
    finalize_piece(-1, out, s_v, s_i);               // sets g_wid = wid0, g_done
    gbar(gen);

    // ---- initial decoder LSTM: ht(step0) -> g_hbuf[1] ----
    lstm_full(WihD, WhhD, bihD, bhhD, embT + (size_t)g_wid * H,
              g_hbuf[0], g_hbuf[1], nullptr, s_g);
    gbar(gen);

    // ---- scores for step 0 ----
    if (b < 16) scores_row(b * NWARP + w, g_hbuf[1]);
    gbar(gen);

    int cur = 1;
    for (int t = 0; t < STEPS; t++) {
        const float* ht   = g_hbuf[cur];
        float*       htn  = g_hbuf[1 - cur];

        // P1: LSTM Whh half (all 512 blocks) || context (blocks 0..3) || finalize(t-1) (block 4)
        lstm_whh(WhhD, ht, s_g);
        context_piece(s_sc, s_a, s_scalar);
        if (t > 0) finalize_piece(t - 1, out, s_v, s_i);
        gbar(gen);

        // P2: LSTM Wih half + pointwise -> ht_{t+1} (uses wid_{t-1}) || proj (blocks 0..127)
        lstm_wih_pw(WihD, embT + (size_t)g_wid * H, bihD, bhhD, htn, nullptr, s_g);
        proj_piece(Wtl, btl, ht);
        gbar(gen);

        // P3: logits (blocks 0..499, streaming) || scores(t+1) from ht_{t+1} (blocks 500..511)
        if (b < NLOGB) {
            logits_piece(Wlt, blt, g_htnew, out_logits + (size_t)t * VOCAB, s_v, s_i);
        } else {
            const int g = (b - SIDE0) * NWARP + w;   // 0..95
            scores_row(g, htn);
            scores_row(g + NSW, htn);
        }
        gbar(gen);

        cur ^= 1;
    }
    finalize_piece(STEPS - 1, out, s_v, s_i);
}

// ---------------- host orchestration ----------------
extern "C" void kernel_launch(void* const* d_in, const int* in_sizes, int n_in,
                              void* d_out, int out_size)
{
    const int*   src  = (const int*)  d_in[0];
    const float* embI = (const float*)d_in[1];
    const float* WihE = (const float*)d_in[2];
    const float* WhhE = (const float*)d_in[3];
    const float* bihE = (const float*)d_in[4];
    const float* bhhE = (const float*)d_in[5];
    const float* Wli  = (const float*)d_in[6];
    const float* bli  = (const float*)d_in[7];
    const float* embT = (const float*)d_in[8];
    const float* WihD = (const float*)d_in[9];
    const float* WhhD = (const float*)d_in[10];
    const float* bihD = (const float*)d_in[11];
    const float* bhhD = (const float*)d_in[12];
    const float* Wlt  = (const float*)d_in[13];
    const float* blt  = (const float*)d_in[14];
    const float* Wtl  = (const float*)d_in[15];
    const float* btl  = (const float*)d_in[16];

    k_init<<<1, 1024>>>();
    k_main<<<GRID, TPB>>>(src, embI, WihE, WhhE, bihE, bhhE, Wli, bli, embT,
                          WihD, WhhD, bihD, bhhD, Wlt, blt, Wtl, btl,
                          (float*)d_out);
}

// round 7
// speedup vs baseline: 1.1866x; 1.0051x over previous
#include <cuda_runtime.h>
#include <math.h>

#define H      1024
#define SLEN   128
#define VOCAB  32000
#define STEPS  51
#define EOS_ID 2
#define GRID   512
#define TPB    256
#define NWARP  8
#define NGRP   500                  // 64-row work groups per logits phase
#define GSZ    64

// ---------------- persistent device state ----------------
__device__ float g_hbuf[2][H];
__device__ float g_c[H];
__device__ float g_hs[SLEN * H];
__device__ float g_scores[SLEN];
__device__ float g_d[H];
__device__ float g_htnew[H];
__device__ float g_pval[GRID];
__device__ int   g_pidx[GRID];
__device__ int   g_wid;
__device__ int   g_done;
__device__ unsigned int g_bar_count;
__device__ unsigned int g_work;      // logits work-stealing counter (monotonic)

__global__ void k_init() {
    int t = threadIdx.x;             // 1024 threads
    g_hbuf[0][t] = 0.f;
    g_c[t] = 0.f;
    if (t == 0) { g_done = 0; g_bar_count = 0u; g_work = 0u; }
}

// ---------------- grid barrier: 1-thread arrival, acq_rel fences, monotonic count ----------------
__device__ __forceinline__ void gbar(unsigned int& gen) {
    __syncthreads();
    gen += GRID;
    if (threadIdx.x == 0) {
        asm volatile("fence.acq_rel.gpu;" ::: "memory");
        unsigned int prev = atomicAdd(&g_bar_count, 1u);
        if (prev + 1u != gen) {
            while (*(volatile unsigned int*)&g_bar_count < gen) { }
        }
        asm volatile("fence.acq_rel.gpu;" ::: "memory");
    }
    __syncthreads();
}

__device__ __forceinline__ float sigf(float x) { return 1.f / (1.f + expf(-x)); }
__device__ __forceinline__ float dp4(float4 a, float4 b) {
    return a.x * b.x + a.y * b.y + a.z * b.z + a.w * b.w;
}
__device__ __forceinline__ float wred(float v) {
#pragma unroll
    for (int o = 16; o; o >>= 1) v += __shfl_down_sync(0xffffffffu, v, o);
    return v;
}

// ---------------- LSTM pieces (blocks 0..511, unit j = b*2 + w/4, gate = w%4) ----------------
__device__ __forceinline__ void lstm_whh(const float* __restrict__ Whh,
                                         const float* __restrict__ hprev, float* s_g)
{
    const int b = blockIdx.x, w = threadIdx.x >> 5, lane = threadIdx.x & 31;
    const int j = b * 2 + (w >> 2), g = w & 3;
    const float4* wh = (const float4*)(Whh + (size_t)(g * H + j) * H);
    const float4* h4 = (const float4*)hprev;
    float acc = 0.f;
#pragma unroll
    for (int i = 0; i < 8; i++) acc += dp4(wh[lane + 32 * i], h4[lane + 32 * i]);
    acc = wred(acc);
    if (!lane) s_g[w] = acc;
}

__device__ __forceinline__ void lstm_pointwise(const float* __restrict__ bih,
                                               const float* __restrict__ bhh,
                                               float* __restrict__ hnext,
                                               float* __restrict__ hs_out, float* s_g)
{
    __syncthreads();
    const int tid = threadIdx.x;
    if (tid < 2) {
        const int j = blockIdx.x * 2 + tid;
        const int base = tid * 4;
        float gi = s_g[base + 0] + bih[j]         + bhh[j];
        float gf = s_g[base + 1] + bih[H + j]     + bhh[H + j];
        float gg = s_g[base + 2] + bih[2 * H + j] + bhh[2 * H + j];
        float go = s_g[base + 3] + bih[3 * H + j] + bhh[3 * H + j];
        float i_ = sigf(gi), f_ = sigf(gf), g_ = tanhf(gg), o_ = sigf(go);
        float c2 = f_ * g_c[j] + i_ * g_;
        g_c[j] = c2;
        float hn = o_ * tanhf(c2);
        hnext[j] = hn;
        if (hs_out) hs_out[j] = hn;
    }
}

// Wih half: adds x-dot into s_g, then pointwise
__device__ __forceinline__ void lstm_wih_pw(const float* __restrict__ Wih,
                                            const float* __restrict__ xrow,
                                            const float* __restrict__ bih,
                                            const float* __restrict__ bhh,
                                            float* __restrict__ hnext,
                                            float* __restrict__ hs_out, float* s_g)
{
    const int b = blockIdx.x, w = threadIdx.x >> 5, lane = threadIdx.x & 31;
    const int j = b * 2 + (w >> 2), g = w & 3;
    const float4* wi = (const float4*)(Wih + (size_t)(g * H + j) * H);
    const float4* x4 = (const float4*)xrow;
    float acc = 0.f;
#pragma unroll
    for (int i = 0; i < 8; i++) acc += dp4(wi[lane + 32 * i], x4[lane + 32 * i]);
    acc = wred(acc);
    if (!lane) s_g[w] += acc;
    lstm_pointwise(bih, bhh, hnext, hs_out, s_g);
}

// full LSTM (encoder / initial decoder step): both halves in one phase
__device__ __forceinline__ void lstm_full(const float* __restrict__ Wih,
                                          const float* __restrict__ Whh,
                                          const float* __restrict__ bih,
                                          const float* __restrict__ bhh,
                                          const float* __restrict__ xrow,
                                          const float* __restrict__ hprev,
                                          float* __restrict__ hnext,
                                          float* __restrict__ hs_out, float* s_g)
{
    const int b = blockIdx.x, w = threadIdx.x >> 5, lane = threadIdx.x & 31;
    const int j = b * 2 + (w >> 2), g = w & 3;
    const float4* wi = (const float4*)(Wih + (size_t)(g * H + j) * H);
    const float4* wh = (const float4*)(Whh + (size_t)(g * H + j) * H);
    const float4* x4 = (const float4*)xrow;
    const float4* h4 = (const float4*)hprev;
    float acc = 0.f;
#pragma unroll
    for (int i = 0; i < 8; i++) acc += dp4(wi[lane + 32 * i], x4[lane + 32 * i]);
#pragma unroll
    for (int i = 0; i < 8; i++) acc += dp4(wh[lane + 32 * i], h4[lane + 32 * i]);
    acc = wred(acc);
    if (!lane) s_g[w] = acc;
    lstm_pointwise(bih, bhh, hnext, hs_out, s_g);
}

// ---------------- attention scores: blocks 496..511, one warp per source row ----------------
__device__ __forceinline__ void scores_piece(const float* __restrict__ ht)
{
    const int b = blockIdx.x;
    if (b < GRID - 16) return;
    const int w = threadIdx.x >> 5, lane = threadIdx.x & 31;
    const int s = (b - (GRID - 16)) * NWARP + w;     // 0..127
    const float4* r  = (const float4*)(g_hs + (size_t)s * H);
    const float4* h4 = (const float4*)ht;
    float acc = 0.f;
#pragma unroll
    for (int i = 0; i < 8; i++) acc += dp4(r[lane + 32 * i], h4[lane + 32 * i]);
    acc = wred(acc);
    if (!lane) g_scores[s] = acc;
}

// ---------------- softmax + context: blocks 0..3 ----------------
__device__ __forceinline__ void context_piece(float* s_sc, float* s_a, float* s_scalar)
{
    const int b = blockIdx.x;
    if (b >= 4) return;
    const int tid = threadIdx.x, w = tid >> 5, lane = tid & 31;
    if (tid < SLEN) s_sc[tid] = g_scores[tid];
    __syncthreads();
    if (w == 0) {
        float m = -INFINITY;
#pragma unroll
        for (int q = 0; q < 4; q++) m = fmaxf(m, s_sc[lane + 32 * q]);
#pragma unroll
        for (int o = 16; o; o >>= 1) m = fmaxf(m, __shfl_xor_sync(0xffffffffu, m, o));
        float sum = 0.f;
#pragma unroll
        for (int q = 0; q < 4; q++) {
            float e = expf(s_sc[lane + 32 * q] - m);
            s_a[lane + 32 * q] = e;
            sum += e;
        }
#pragma unroll
        for (int o = 16; o; o >>= 1) sum += __shfl_xor_sync(0xffffffffu, sum, o);
        if (!lane) s_scalar[0] = 1.f / sum;
    }
    __syncthreads();
    const float inv = s_scalar[0];
    const int j = b * TPB + threadIdx.x;
    float acc = 0.f;
#pragma unroll 8
    for (int s = 0; s < SLEN; s++) acc += s_a[s] * g_hs[(size_t)s * H + j];
    g_d[j] = acc * inv;
}

// ---------------- proj: blocks 0..127, warp-per-row ----------------
__device__ __forceinline__ void proj_piece(const float* __restrict__ Wtl,
                                           const float* __restrict__ btl,
                                           const float* __restrict__ ht)
{
    const int b = blockIdx.x;
    if (b >= 128) return;
    const int w = threadIdx.x >> 5, lane = threadIdx.x & 31;
    const int r = b * NWARP + w;                     // 0..1023
    const float4* wr = (const float4*)(Wtl + (size_t)r * 2 * H);
    const float4* d4 = (const float4*)g_d;
    const float4* h4 = (const float4*)ht;
    float acc = 0.f;
#pragma unroll
    for (int i = 0; i < 8; i++) acc += dp4(wr[lane + 32 * i], d4[lane + 32 * i]);
#pragma unroll
    for (int i = 0; i < 8; i++) acc += dp4(wr[256 + lane + 32 * i], h4[lane + 32 * i]);
    acc = wred(acc);
    if (!lane) g_htnew[r] = tanhf(acc + btl[r]);
}

// ---------------- logits GEMV with dynamic work stealing (all 512 blocks) ----------------
// 500 groups of 64 rows; blocks grab groups from g_work until exhausted.
// Increments per phase are deterministic: NGRP successes + GRID failures (one per block).
__device__ __forceinline__ void logits_steal(const float* __restrict__ W,
                                             const float* __restrict__ bias,
                                             const float* __restrict__ vec,
                                             float* __restrict__ out_logits,
                                             unsigned int wbase,
                                             float* s_v, int* s_i, int* s_grp)
{
    const int tid = threadIdx.x, w = tid >> 5, lane = tid & 31;
    const float4* x4 = (const float4*)vec;
    float4 v[8];
#pragma unroll
    for (int q = 0; q < 8; q++) v[q] = x4[lane + 32 * q];

    float best = -INFINITY; int bidx = VOCAB;
    for (;;) {
        if (tid == 0) s_grp[0] = (int)(atomicAdd(&g_work, 1u) - wbase);
        __syncthreads();
        const int grp = s_grp[0];
        __syncthreads();
        if (grp >= NGRP) break;
        const int r0 = grp * GSZ + w * 8;            // warp owns 8 consecutive rows
#pragma unroll
        for (int i = 0; i < 8; i++) {
            const int r = r0 + i;                    // ascending within group
            const float4* wr = (const float4*)(W + (size_t)r * H);
            float acc = 0.f;
#pragma unroll
            for (int q = 0; q < 8; q++) acc += dp4(__ldcs(wr + lane + 32 * q), v[q]);
            acc = wred(acc);
            if (!lane) {
                float lg = acc + bias[r];
                if (out_logits) __stcs(out_logits + r, lg);
                if (lg > best || (lg == best && r < bidx)) { best = lg; bidx = r; }
            }
        }
    }
    if (!lane) { s_v[w] = best; s_i[w] = bidx; }
    __syncthreads();
    if (tid == 0) {
        float bv = s_v[0]; int bi = s_i[0];
#pragma unroll
        for (int q = 1; q < NWARP; q++)
            if (s_v[q] > bv || (s_v[q] == bv && s_i[q] < bi)) { bv = s_v[q]; bi = s_i[q]; }
        g_pval[blockIdx.x] = bv; g_pidx[blockIdx.x] = bi;
    }
}

// ---------------- final argmax + token emit (block 4) ----------------
__device__ __forceinline__ void finalize_piece(int step, float* __restrict__ out_toks,
                                               float* s_v, int* s_i)
{
    if (blockIdx.x != 4) return;
    const int t = threadIdx.x;
    float bv = g_pval[t];       int bi = g_pidx[t];
    float v2 = g_pval[t + 256]; int i2 = g_pidx[t + 256];
    if (v2 > bv || (v2 == bv && i2 < bi)) { bv = v2; bi = i2; }
    s_v[t] = bv; s_i[t] = bi;
    __syncthreads();
    for (int st = 128; st > 0; st >>= 1) {
        if (t < st) {
            float v = s_v[t + st]; int i = s_i[t + st];
            if (v > s_v[t] || (v == s_v[t] && i < s_i[t])) { s_v[t] = v; s_i[t] = i; }
        }
        __syncthreads();
    }
    if (t == 0) {
        int wid = s_i[0];
        int done_prev = (step >= 0) ? g_done : 0;
        int is_eos = (wid == EOS_ID);
        if (step >= 0) out_toks[step] = (float)((done_prev || is_eos) ? -1 : wid);
        g_wid = wid;
        g_done = done_prev | is_eos;
    }
    __syncthreads();
}

// ---------------- the whole model, one persistent kernel ----------------
__global__ void __launch_bounds__(TPB, 4) k_main(
    const int* __restrict__ src,
    const float* __restrict__ embI,
    const float* __restrict__ WihE, const float* __restrict__ WhhE,
    const float* __restrict__ bihE, const float* __restrict__ bhhE,
    const float* __restrict__ Wli,  const float* __restrict__ bli,
    const float* __restrict__ embT,
    const float* __restrict__ WihD, const float* __restrict__ WhhD,
    const float* __restrict__ bihD, const float* __restrict__ bhhD,
    const float* __restrict__ Wlt,  const float* __restrict__ blt,
    const float* __restrict__ Wtl,  const float* __restrict__ btl,
    float* __restrict__ out)
{
    __shared__ float s_g[8];         // gate partials; PERSISTS across the P1->P2 grid barrier
    __shared__ float s_v[256];
    __shared__ int   s_i[256];
    __shared__ float s_sc[SLEN];
    __shared__ float s_a[SLEN];
    __shared__ float s_scalar[1];
    __shared__ int   s_grp[1];

    unsigned int gen = 0;
    unsigned int wbase = 0;          // work counter base; advances NGRP+GRID per logits phase
    float* out_logits = out + STEPS;

    // ---- encoder: 128 sequential full-LSTM phases ----
    for (int t = 0; t < SLEN; t++) {
        lstm_full(WihE, WhhE, bihE, bhhE, embI + (size_t)src[t] * H,
                  g_hbuf[t & 1], g_hbuf[(t + 1) & 1], g_hs + (size_t)t * H, s_g);
        gbar(gen);
    }
    // final encoder h in g_hbuf[0], c in g_c

    // ---- first word ----
    logits_steal(Wli, bli, g_hbuf[0], nullptr, wbase, s_v, s_i, s_grp);
    wbase += NGRP + GRID;
    gbar(gen);
    finalize_piece(-1, out, s_v, s_i);               // sets g_wid = wid0, g_done
    gbar(gen);

    // ---- initial decoder LSTM: ht(step0) -> g_hbuf[1] ----
    lstm_full(WihD, WhhD, bihD, bhhD, embT + (size_t)g_wid * H,
              g_hbuf[0], g_hbuf[1], nullptr, s_g);
    gbar(gen);

    // ---- scores for step 0 ----
    scores_piece(g_hbuf[1]);
    gbar(gen);

    int cur = 1;
    for (int t = 0; t < STEPS; t++) {
        const float* ht   = g_hbuf[cur];
        float*       htn  = g_hbuf[1 - cur];

        // P1: LSTM Whh half (all 512 blocks) || context (blocks 0..3) || finalize(t-1) (block 4)
        lstm_whh(WhhD, ht, s_g);
        context_piece(s_sc, s_a, s_scalar);
        if (t > 0) finalize_piece(t - 1, out, s_v, s_i);
        gbar(gen);

        // P2: LSTM Wih half + pointwise -> ht_{t+1} (uses wid_{t-1}) || proj (blocks 0..127)
        lstm_wih_pw(WihD, embT + (size_t)g_wid * H, bihD, bhhD, htn, nullptr, s_g);
        proj_piece(Wtl, btl, ht);
        gbar(gen);

        // P3: scores(t+1) on blocks 496..511 first, then EVERY block steals logits groups
        scores_piece(htn);
        logits_steal(Wlt, blt, g_htnew, out_logits + (size_t)t * VOCAB, wbase, s_v, s_i, s_grp);
        wbase += NGRP + GRID;
        gbar(gen);

        cur ^= 1;
    }
    finalize_piece(STEPS - 1, out, s_v, s_i);
}

// ---------------- host orchestration ----------------
extern "C" void kernel_launch(void* const* d_in, const int* in_sizes, int n_in,
                              void* d_out, int out_size)
{
    const int*   src  = (const int*)  d_in[0];
    const float* embI = (const float*)d_in[1];
    const float* WihE = (const float*)d_in[2];
    const float* WhhE = (const float*)d_in[3];
    const float* bihE = (const float*)d_in[4];
    const float* bhhE = (const float*)d_in[5];
    const float* Wli  = (const float*)d_in[6];
    const float* bli  = (const float*)d_in[7];
    const float* embT = (const float*)d_in[8];
    const float* WihD = (const float*)d_in[9];
    const float* WhhD = (const float*)d_in[10];
    const float* bihD = (const float*)d_in[11];
    const float* bhhD = (const float*)d_in[12];
    const float* Wlt  = (const float*)d_in[13];
    const float* blt  = (const float*)d_in[14];
    const float* Wtl  = (const float*)d_in[15];
    const float* btl  = (const float*)d_in[16];

    k_init<<<1, 1024>>>();
    k_main<<<GRID, TPB>>>(src, embI, WihE, WhhE, bihE, bhhE, Wli, bli, embT,
                          WihD, WhhD, bihD, bhhD, Wlt, blt, Wtl, btl,
                          (float*)d_out);
}

// round 8
// speedup vs baseline: 1.2329x; 1.0390x over previous
#include <cuda_runtime.h>
#include <math.h>

#define H      1024
#define SLEN   128
#define VOCAB  32000
#define STEPS  51
#define EOS_ID 2
#define GRID   512
#define TPB    256
#define NWARP  8
#define NWT    4096                  // total warps

// ---------------- persistent device state ----------------
__device__ float g_hbuf[2][H];
__device__ float g_c[H];
__device__ float g_hs[SLEN * H];
__device__ float g_gih[SLEN * 4 * H];   // precomputed Wih_e @ x_t (gate-major rows)
__device__ float g_scores[SLEN];
__device__ float g_d[H];
__device__ float g_htnew[H];
__device__ float g_pval[GRID];
__device__ int   g_pidx[GRID];
__device__ int   g_wid;
__device__ int   g_done;
__device__ unsigned int g_bar_count;

__global__ void k_init() {
    int t = threadIdx.x;             // 1024 threads
    g_hbuf[0][t] = 0.f;
    g_c[t] = 0.f;
    if (t == 0) { g_done = 0; g_bar_count = 0u; }
}

// ---------------- grid barrier: 1-thread arrival, acq_rel fences, monotonic count ----------------
__device__ __forceinline__ void gbar(unsigned int& gen) {
    __syncthreads();
    gen += GRID;
    if (threadIdx.x == 0) {
        asm volatile("fence.acq_rel.gpu;" ::: "memory");
        unsigned int prev = atomicAdd(&g_bar_count, 1u);
        if (prev + 1u != gen) {
            while (*(volatile unsigned int*)&g_bar_count < gen) { }
        }
        asm volatile("fence.acq_rel.gpu;" ::: "memory");
    }
    __syncthreads();
}

__device__ __forceinline__ float sigf(float x) { return 1.f / (1.f + expf(-x)); }
__device__ __forceinline__ float dp4(float4 a, float4 b) {
    return a.x * b.x + a.y * b.y + a.z * b.z + a.w * b.w;
}
__device__ __forceinline__ float wred(float v) {
#pragma unroll
    for (int o = 16; o; o >>= 1) v += __shfl_down_sync(0xffffffffu, v, o);
    return v;
}

// ---------------- LSTM pieces (blocks 0..511, unit j = b*2 + w/4, gate = w%4) ----------------
__device__ __forceinline__ void lstm_whh(const float* __restrict__ Whh,
                                         const float* __restrict__ hprev, float* s_g)
{
    const int b = blockIdx.x, w = threadIdx.x >> 5, lane = threadIdx.x & 31;
    const int j = b * 2 + (w >> 2), g = w & 3;
    const float4* wh = (const float4*)(Whh + (size_t)(g * H + j) * H);
    const float4* h4 = (const float4*)hprev;
    float acc = 0.f;
#pragma unroll
    for (int i = 0; i < 8; i++) acc += dp4(wh[lane + 32 * i], h4[lane + 32 * i]);
    acc = wred(acc);
    if (!lane) s_g[w] = acc;
}

// decoder pointwise (gates fully in s_g)
__device__ __forceinline__ void lstm_pointwise(const float* __restrict__ bih,
                                               const float* __restrict__ bhh,
                                               float* __restrict__ hnext,
                                               float* __restrict__ hs_out, float* s_g)
{
    __syncthreads();
    const int tid = threadIdx.x;
    if (tid < 2) {
        const int j = blockIdx.x * 2 + tid;
        const int base = tid * 4;
        float gi = s_g[base + 0] + bih[j]         + bhh[j];
        float gf = s_g[base + 1] + bih[H + j]     + bhh[H + j];
        float gg = s_g[base + 2] + bih[2 * H + j] + bhh[2 * H + j];
        float go = s_g[base + 3] + bih[3 * H + j] + bhh[3 * H + j];
        float i_ = sigf(gi), f_ = sigf(gf), g_ = tanhf(gg), o_ = sigf(go);
        float c2 = f_ * g_c[j] + i_ * g_;
        g_c[j] = c2;
        float hn = o_ * tanhf(c2);
        hnext[j] = hn;
        if (hs_out) hs_out[j] = hn;
    }
}

// encoder pointwise: adds precomputed Wih@x term from g_gih[t]
__device__ __forceinline__ void lstm_pointwise_pre(int t,
                                                   const float* __restrict__ bih,
                                                   const float* __restrict__ bhh,
                                                   float* __restrict__ hnext,
                                                   float* __restrict__ hs_out, float* s_g)
{
    __syncthreads();
    const int tid = threadIdx.x;
    if (tid < 2) {
        const int j = blockIdx.x * 2 + tid;
        const int base = tid * 4;
        const float* pre = g_gih + (size_t)t * (4 * H);
        float gi = s_g[base + 0] + pre[j]         + bih[j]         + bhh[j];
        float gf = s_g[base + 1] + pre[H + j]     + bih[H + j]     + bhh[H + j];
        float gg = s_g[base + 2] + pre[2 * H + j] + bih[2 * H + j] + bhh[2 * H + j];
        float go = s_g[base + 3] + pre[3 * H + j] + bih[3 * H + j] + bhh[3 * H + j];
        float i_ = sigf(gi), f_ = sigf(gf), g_ = tanhf(gg), o_ = sigf(go);
        float c2 = f_ * g_c[j] + i_ * g_;
        g_c[j] = c2;
        float hn = o_ * tanhf(c2);
        hnext[j] = hn;
        if (hs_out) hs_out[j] = hn;
    }
}

// Wih half: adds x-dot into s_g, then pointwise (decoder steps)
__device__ __forceinline__ void lstm_wih_pw(const float* __restrict__ Wih,
                                            const float* __restrict__ xrow,
                                            const float* __restrict__ bih,
                                            const float* __restrict__ bhh,
                                            float* __restrict__ hnext,
                                            float* __restrict__ hs_out, float* s_g)
{
    const int b = blockIdx.x, w = threadIdx.x >> 5, lane = threadIdx.x & 31;
    const int j = b * 2 + (w >> 2), g = w & 3;
    const float4* wi = (const float4*)(Wih + (size_t)(g * H + j) * H);
    const float4* x4 = (const float4*)xrow;
    float acc = 0.f;
#pragma unroll
    for (int i = 0; i < 8; i++) acc += dp4(wi[lane + 32 * i], x4[lane + 32 * i]);
    acc = wred(acc);
    if (!lane) s_g[w] += acc;
    lstm_pointwise(bih, bhh, hnext, hs_out, s_g);
}

// full LSTM (initial decoder step): both halves in one phase
__device__ __forceinline__ void lstm_full(const float* __restrict__ Wih,
                                          const float* __restrict__ Whh,
                                          const float* __restrict__ bih,
                                          const float* __restrict__ bhh,
                                          const float* __restrict__ xrow,
                                          const float* __restrict__ hprev,
                                          float* __restrict__ hnext,
                                          float* __restrict__ hs_out, float* s_g)
{
    const int b = blockIdx.x, w = threadIdx.x >> 5, lane = threadIdx.x & 31;
    const int j = b * 2 + (w >> 2), g = w & 3;
    const float4* wi = (const float4*)(Wih + (size_t)(g * H + j) * H);
    const float4* wh = (const float4*)(Whh + (size_t)(g * H + j) * H);
    const float4* x4 = (const float4*)xrow;
    const float4* h4 = (const float4*)hprev;
    float acc = 0.f;
#pragma unroll
    for (int i = 0; i < 8; i++) acc += dp4(wi[lane + 32 * i], x4[lane + 32 * i]);
#pragma unroll
    for (int i = 0; i < 8; i++) acc += dp4(wh[lane + 32 * i], h4[lane + 32 * i]);
    acc = wred(acc);
    if (!lane) s_g[w] = acc;
    lstm_pointwise(bih, bhh, hnext, hs_out, s_g);
}

// ---------------- attention scores: blocks 496..511, one warp per source row ----------------
__device__ __forceinline__ void scores_piece(const float* __restrict__ ht)
{
    const int b = blockIdx.x;
    if (b < GRID - 16) return;
    const int w = threadIdx.x >> 5, lane = threadIdx.x & 31;
    const int s = (b - (GRID - 16)) * NWARP + w;     // 0..127
    const float4* r  = (const float4*)(g_hs + (size_t)s * H);
    const float4* h4 = (const float4*)ht;
    float acc = 0.f;
#pragma unroll
    for (int i = 0; i < 8; i++) acc += dp4(r[lane + 32 * i], h4[lane + 32 * i]);
    acc = wred(acc);
    if (!lane) g_scores[s] = acc;
}

// ---------------- softmax + context: blocks 0..3 ----------------
__device__ __forceinline__ void context_piece(float* s_sc, float* s_a, float* s_scalar)
{
    const int b = blockIdx.x;
    if (b >= 4) return;
    const int tid = threadIdx.x, w = tid >> 5, lane = tid & 31;
    if (tid < SLEN) s_sc[tid] = g_scores[tid];
    __syncthreads();
    if (w == 0) {
        float m = -INFINITY;
#pragma unroll
        for (int q = 0; q < 4; q++) m = fmaxf(m, s_sc[lane + 32 * q]);
#pragma unroll
        for (int o = 16; o; o >>= 1) m = fmaxf(m, __shfl_xor_sync(0xffffffffu, m, o));
        float sum = 0.f;
#pragma unroll
        for (int q = 0; q < 4; q++) {
            float e = expf(s_sc[lane + 32 * q] - m);
            s_a[lane + 32 * q] = e;
            sum += e;
        }
#pragma unroll
        for (int o = 16; o; o >>= 1) sum += __shfl_xor_sync(0xffffffffu, sum, o);
        if (!lane) s_scalar[0] = 1.f / sum;
    }
    __syncthreads();
    const float inv = s_scalar[0];
    const int j = b * TPB + threadIdx.x;
    float acc = 0.f;
#pragma unroll 8
    for (int s = 0; s < SLEN; s++) acc += s_a[s] * g_hs[(size_t)s * H + j];
    g_d[j] = acc * inv;
}

// ---------------- proj: blocks 0..127, warp-per-row ----------------
__device__ __forceinline__ void proj_piece(const float* __restrict__ Wtl,
                                           const float* __restrict__ btl,
                                           const float* __restrict__ ht)
{
    const int b = blockIdx.x;
    if (b >= 128) return;
    const int w = threadIdx.x >> 5, lane = threadIdx.x & 31;
    const int r = b * NWARP + w;                     // 0..1023
    const float4* wr = (const float4*)(Wtl + (size_t)r * 2 * H);
    const float4* d4 = (const float4*)g_d;
    const float4* h4 = (const float4*)ht;
    float acc = 0.f;
#pragma unroll
    for (int i = 0; i < 8; i++) acc += dp4(wr[lane + 32 * i], d4[lane + 32 * i]);
#pragma unroll
    for (int i = 0; i < 8; i++) acc += dp4(wr[256 + lane + 32 * i], h4[lane + 32 * i]);
    acc = wred(acc);
    if (!lane) g_htnew[r] = tanhf(acc + btl[r]);
}

// ---------------- logits GEMV: round-3 slab mapping + 2-row interleave ----------------
// warp gw owns rows {gw + 4096*i, i=0..7}, processed as pairs (gw+8192p, gw+8192p+4096).
__device__ __forceinline__ void logits_piece(const float* __restrict__ W,
                                             const float* __restrict__ bias,
                                             const float* __restrict__ vec,
                                             float* __restrict__ out_logits,
                                             float* s_v, int* s_i)
{
    const int tid = threadIdx.x, w = tid >> 5, lane = tid & 31;
    const float4* x4 = (const float4*)vec;
    float4 v[8];
#pragma unroll
    for (int q = 0; q < 8; q++) v[q] = x4[lane + 32 * q];
    const int gw = blockIdx.x * NWARP + w;           // 0..4095
    float best = -INFINITY; int bidx = VOCAB;
#pragma unroll
    for (int p = 0; p < 4; p++) {
        const int r0 = gw + 8192 * p;                // always < VOCAB (max 28671)
        const int r1 = r0 + 4096;                    // may exceed VOCAB-1 at p=3
        const float4* w0 = (const float4*)(W + (size_t)r0 * H);
        if (r1 < VOCAB) {
            const float4* w1 = (const float4*)(W + (size_t)r1 * H);
            float acc0 = 0.f, acc1 = 0.f;
#pragma unroll
            for (int q = 0; q < 8; q++) {
                const int k = lane + 32 * q;
                float4 a = __ldcs(w0 + k);
                float4 b = __ldcs(w1 + k);
                acc0 += dp4(a, v[q]);
                acc1 += dp4(b, v[q]);
            }
            acc0 = wred(acc0);
            acc1 = wred(acc1);
            if (!lane) {
                float l0 = acc0 + bias[r0];
                float l1 = acc1 + bias[r1];
                if (out_logits) { __stcs(out_logits + r0, l0); __stcs(out_logits + r1, l1); }
                if (l0 > best) { best = l0; bidx = r0; }   // r0 < r1: order preserves tie-break
                if (l1 > best) { best = l1; bidx = r1; }
            }
        } else {
            float acc0 = 0.f;
#pragma unroll
            for (int q = 0; q < 8; q++) acc0 += dp4(__ldcs(w0 + lane + 32 * q), v[q]);
            acc0 = wred(acc0);
            if (!lane) {
                float l0 = acc0 + bias[r0];
                if (out_logits) __stcs(out_logits + r0, l0);
                if (l0 > best) { best = l0; bidx = r0; }
            }
        }
    }
    if (!lane) { s_v[w] = best; s_i[w] = bidx; }
    __syncthreads();
    if (tid == 0) {
        float bv = s_v[0]; int bi = s_i[0];
#pragma unroll
        for (int q = 1; q < NWARP; q++)
            if (s_v[q] > bv || (s_v[q] == bv && s_i[q] < bi)) { bv = s_v[q]; bi = s_i[q]; }
        g_pval[blockIdx.x] = bv; g_pidx[blockIdx.x] = bi;
    }
}

// ---------------- final argmax + token emit (block 4) ----------------
__device__ __forceinline__ void finalize_piece(int step, float* __restrict__ out_toks,
                                               float* s_v, int* s_i)
{
    if (blockIdx.x != 4) return;
    const int t = threadIdx.x;
    float bv = g_pval[t];       int bi = g_pidx[t];
    float v2 = g_pval[t + 256]; int i2 = g_pidx[t + 256];
    if (v2 > bv || (v2 == bv && i2 < bi)) { bv = v2; bi = i2; }
    s_v[t] = bv; s_i[t] = bi;
    __syncthreads();
    for (int st = 128; st > 0; st >>= 1) {
        if (t < st) {
            float v = s_v[t + st]; int i = s_i[t + st];
            if (v > s_v[t] || (v == s_v[t] && i < s_i[t])) { s_v[t] = v; s_i[t] = i; }
        }
        __syncthreads();
    }
    if (t == 0) {
        int wid = s_i[0];
        int done_prev = (step >= 0) ? g_done : 0;
        int is_eos = (wid == EOS_ID);
        if (step >= 0) out_toks[step] = (float)((done_prev || is_eos) ? -1 : wid);
        g_wid = wid;
        g_done = done_prev | is_eos;
    }
    __syncthreads();
}

// ---------------- the whole model, one persistent kernel ----------------
__global__ void __launch_bounds__(TPB, 4) k_main(
    const int* __restrict__ src,
    const float* __restrict__ embI,
    const float* __restrict__ WihE, const float* __restrict__ WhhE,
    const float* __restrict__ bihE, const float* __restrict__ bhhE,
    const float* __restrict__ Wli,  const float* __restrict__ bli,
    const float* __restrict__ embT,
    const float* __restrict__ WihD, const float* __restrict__ WhhD,
    const float* __restrict__ bihD, const float* __restrict__ bhhD,
    const float* __restrict__ Wlt,  const float* __restrict__ blt,
    const float* __restrict__ Wtl,  const float* __restrict__ btl,
    float* __restrict__ out)
{
    __shared__ float s_g[8];         // gate partials; PERSISTS across the P1->P2 grid barrier
    __shared__ float s_v[256];
    __shared__ int   s_i[256];
    __shared__ float s_sc[SLEN];
    __shared__ float s_a[SLEN];
    __shared__ float s_scalar[1];

    unsigned int gen = 0;
    float* out_logits = out + STEPS;
    const int b = blockIdx.x;
    const int w = threadIdx.x >> 5, lane = threadIdx.x & 31;

    // ---- P0: precompute Wih_e @ x_t for all 128 tokens; warp owns Wih row r = b*8+w ----
    {
        const int r = b * NWARP + w;                 // 0..4095 (gate-major Wih row)
        const float4* wr = (const float4*)(WihE + (size_t)r * H);
        float4 wreg[8];
#pragma unroll
        for (int q = 0; q < 8; q++) wreg[q] = wr[lane + 32 * q];
        for (int t = 0; t < SLEN; t += 2) {
            const float4* x0 = (const float4*)(embI + (size_t)src[t]     * H);
            const float4* x1 = (const float4*)(embI + (size_t)src[t + 1] * H);
            float a0 = 0.f, a1 = 0.f;
#pragma unroll
            for (int q = 0; q < 8; q++) {
                const int k = lane + 32 * q;
                a0 += dp4(wreg[q], x0[k]);
                a1 += dp4(wreg[q], x1[k]);
            }
            a0 = wred(a0);
            a1 = wred(a1);
            if (!lane) {
                g_gih[(size_t)t       * (4 * H) + r] = a0;
                g_gih[(size_t)(t + 1) * (4 * H) + r] = a1;
            }
        }
    }
    gbar(gen);

    // ---- encoder: 128 steps, Whh-only GEMV + precomputed Wih term ----
    for (int t = 0; t < SLEN; t++) {
        lstm_whh(WhhE, g_hbuf[t & 1], s_g);
        lstm_pointwise_pre(t, bihE, bhhE, g_hbuf[(t + 1) & 1], g_hs + (size_t)t * H, s_g);
        gbar(gen);
    }
    // final encoder h in g_hbuf[0], c in g_c

    // ---- first word ----
    logits_piece(Wli, bli, g_hbuf[0], nullptr, s_v, s_i);
    gbar(gen);
    finalize_piece(-1, out, s_v, s_i);               // sets g_wid = wid0, g_done
    gbar(gen);

    // ---- initial decoder LSTM: ht(step0) -> g_hbuf[1] ----
    lstm_full(WihD, WhhD, bihD, bhhD, embT + (size_t)g_wid * H,
              g_hbuf[0], g_hbuf[1], nullptr, s_g);
    gbar(gen);

    // ---- scores for step 0 ----
    scores_piece(g_hbuf[1]);
    gbar(gen);

    int cur = 1;
    for (int t = 0; t < STEPS; t++) {
        const float* ht   = g_hbuf[cur];
        float*       htn  = g_hbuf[1 - cur];

        // P1: LSTM Whh half (all 512 blocks) || context (blocks 0..3) || finalize(t-1) (block 4)
        lstm_whh(WhhD, ht, s_g);
        context_piece(s_sc, s_a, s_scalar);
        if (t > 0) finalize_piece(t - 1, out, s_v, s_i);
        gbar(gen);

        // P2: LSTM Wih half + pointwise -> ht_{t+1} (uses wid_{t-1}) || proj (blocks 0..127)
        lstm_wih_pw(WihD, embT + (size_t)g_wid * H, bihD, bhhD, htn, nullptr, s_g);
        proj_piece(Wtl, btl, ht);
        gbar(gen);

        // P3: logits (all blocks, streaming) || scores(t+1) from ht_{t+1} (blocks 496..511)
        scores_piece(htn);
        logits_piece(Wlt, blt, g_htnew, out_logits + (size_t)t * VOCAB, s_v, s_i);
        gbar(gen);

        cur ^= 1;
    }
    finalize_piece(STEPS - 1, out, s_v, s_i);
}

// ---------------- host orchestration ----------------
extern "C" void kernel_launch(void* const* d_in, const int* in_sizes, int n_in,
                              void* d_out, int out_size)
{
    const int*   src  = (const int*)  d_in[0];
    const float* embI = (const float*)d_in[1];
    const float* WihE = (const float*)d_in[2];
    const float* WhhE = (const float*)d_in[3];
    const float* bihE = (const float*)d_in[4];
    const float* bhhE = (const float*)d_in[5];
    const float* Wli  = (const float*)d_in[6];
    const float* bli  = (const float*)d_in[7];
    const float* embT = (const float*)d_in[8];
    const float* WihD = (const float*)d_in[9];
    const float* WhhD = (const float*)d_in[10];
    const float* bihD = (const float*)d_in[11];
    const float* bhhD = (const float*)d_in[12];
    const float* Wlt  = (const float*)d_in[13];
    const float* blt  = (const float*)d_in[14];
    const float* Wtl  = (const float*)d_in[15];
    const float* btl  = (const float*)d_in[16];

    k_init<<<1, 1024>>>();
    k_main<<<GRID, TPB>>>(src, embI, WihE, WhhE, bihE, bhhE, Wli, bli, embT,
                          WihD, WhhD, bihD, bhhD, Wlt, blt, Wtl, btl,
                          (float*)d_out);
}

// round 9
// speedup vs baseline: 1.3688x; 1.1103x over previous
#include <cuda_runtime.h>
#include <math.h>

#define H      1024
#define SLEN   128
#define VOCAB  32000
#define STEPS  51
#define EOS_ID 2
#define GRID   512
#define TPB    256
#define NWARP  8
#define COMB0  256                   // blocks [256..511] compute ht2 columns in phase A

// ---------------- persistent device state ----------------
__device__ float g_hbuf[2][H];
__device__ float g_c[H];
__device__ float g_hs[SLEN * H];
__device__ float g_gih[SLEN * 4 * H];   // precomputed Wih_e @ x_t
__device__ float g_U[H * SLEN];         // U[j][s] = Wtl_d[j] . hs[s]
__device__ float g_scores[SLEN];
__device__ float g_ht2[H];
__device__ float g_pval[GRID];
__device__ int   g_pidx[GRID];
__device__ unsigned int g_bar_count;

__global__ void k_init() {
    int t = threadIdx.x;             // 1024 threads
    g_hbuf[0][t] = 0.f;
    g_c[t] = 0.f;
    if (t == 0) g_bar_count = 0u;
}

// ---------------- grid barrier ----------------
__device__ __forceinline__ void gbar(unsigned int& gen) {
    __syncthreads();
    gen += GRID;
    if (threadIdx.x == 0) {
        asm volatile("fence.acq_rel.gpu;" ::: "memory");
        unsigned int prev = atomicAdd(&g_bar_count, 1u);
        if (prev + 1u != gen) {
            while (*(volatile unsigned int*)&g_bar_count < gen) { }
        }
        asm volatile("fence.acq_rel.gpu;" ::: "memory");
    }
    __syncthreads();
}

__device__ __forceinline__ float sigf(float x) { return 1.f / (1.f + expf(-x)); }
__device__ __forceinline__ float dp4(float4 a, float4 b) {
    return a.x * b.x + a.y * b.y + a.z * b.z + a.w * b.w;
}
__device__ __forceinline__ float wred(float v) {
#pragma unroll
    for (int o = 16; o; o >>= 1) v += __shfl_down_sync(0xffffffffu, v, o);
    return v;
}

// ---------------- LSTM: full cell, block b owns units 2b,2b+1; warp = one gate row ----------------
__device__ __forceinline__ void lstm_whh(const float* __restrict__ Whh,
                                         const float* __restrict__ hprev, float* s_g)
{
    const int b = blockIdx.x, w = threadIdx.x >> 5, lane = threadIdx.x & 31;
    const int j = b * 2 + (w >> 2), g = w & 3;
    const float4* wh = (const float4*)(Whh + (size_t)(g * H + j) * H);
    const float4* h4 = (const float4*)hprev;
    float acc = 0.f;
#pragma unroll
    for (int i = 0; i < 8; i++) acc += dp4(wh[lane + 32 * i], h4[lane + 32 * i]);
    acc = wred(acc);
    if (!lane) s_g[w] = acc;
}

__device__ __forceinline__ void lstm_pointwise(const float* __restrict__ bih,
                                               const float* __restrict__ bhh,
                                               float* __restrict__ hnext,
                                               float* __restrict__ hs_out, float* s_g)
{
    __syncthreads();
    const int tid = threadIdx.x;
    if (tid < 2) {
        const int j = blockIdx.x * 2 + tid;
        const int base = tid * 4;
        float gi = s_g[base + 0] + bih[j]         + bhh[j];
        float gf = s_g[base + 1] + bih[H + j]     + bhh[H + j];
        float gg = s_g[base + 2] + bih[2 * H + j] + bhh[2 * H + j];
        float go = s_g[base + 3] + bih[3 * H + j] + bhh[3 * H + j];
        float i_ = sigf(gi), f_ = sigf(gf), g_ = tanhf(gg), o_ = sigf(go);
        float c2 = f_ * g_c[j] + i_ * g_;
        g_c[j] = c2;
        float hn = o_ * tanhf(c2);
        hnext[j] = hn;
        if (hs_out) hs_out[j] = hn;
    }
}

// encoder pointwise: adds precomputed Wih@x term from g_gih[t]
__device__ __forceinline__ void lstm_pointwise_pre(int t,
                                                   const float* __restrict__ bih,
                                                   const float* __restrict__ bhh,
                                                   float* __restrict__ hnext,
                                                   float* __restrict__ hs_out, float* s_g)
{
    __syncthreads();
    const int tid = threadIdx.x;
    if (tid < 2) {
        const int j = blockIdx.x * 2 + tid;
        const int base = tid * 4;
        const float* pre = g_gih + (size_t)t * (4 * H);
        float gi = s_g[base + 0] + pre[j]         + bih[j]         + bhh[j];
        float gf = s_g[base + 1] + pre[H + j]     + bih[H + j]     + bhh[H + j];
        float gg = s_g[base + 2] + pre[2 * H + j] + bih[2 * H + j] + bhh[2 * H + j];
        float go = s_g[base + 3] + pre[3 * H + j] + bih[3 * H + j] + bhh[3 * H + j];
        float i_ = sigf(gi), f_ = sigf(gf), g_ = tanhf(gg), o_ = sigf(go);
        float c2 = f_ * g_c[j] + i_ * g_;
        g_c[j] = c2;
        float hn = o_ * tanhf(c2);
        hnext[j] = hn;
        if (hs_out) hs_out[j] = hn;
    }
}

// full LSTM cell: both halves + pointwise in one phase
__device__ __forceinline__ void lstm_full(const float* __restrict__ Wih,
                                          const float* __restrict__ Whh,
                                          const float* __restrict__ bih,
                                          const float* __restrict__ bhh,
                                          const float* __restrict__ xrow,
                                          const float* __restrict__ hprev,
                                          float* __restrict__ hnext,
                                          float* __restrict__ hs_out, float* s_g)
{
    const int b = blockIdx.x, w = threadIdx.x >> 5, lane = threadIdx.x & 31;
    const int j = b * 2 + (w >> 2), g = w & 3;
    const float4* wi = (const float4*)(Wih + (size_t)(g * H + j) * H);
    const float4* wh = (const float4*)(Whh + (size_t)(g * H + j) * H);
    const float4* x4 = (const float4*)xrow;
    const float4* h4 = (const float4*)hprev;
    float acc = 0.f;
#pragma unroll
    for (int i = 0; i < 8; i++) acc += dp4(wi[lane + 32 * i], x4[lane + 32 * i]);
#pragma unroll
    for (int i = 0; i < 8; i++) acc += dp4(wh[lane + 32 * i], h4[lane + 32 * i]);
    acc = wred(acc);
    if (!lane) s_g[w] = acc;
    lstm_pointwise(bih, bhh, hnext, hs_out, s_g);
}

// ---------------- attention scores: blocks 496..511, one warp per source row ----------------
__device__ __forceinline__ void scores_piece(const float* __restrict__ ht)
{
    const int b = blockIdx.x;
    if (b < GRID - 16) return;
    const int w = threadIdx.x >> 5, lane = threadIdx.x & 31;
    const int s = (b - (GRID - 16)) * NWARP + w;     // 0..127
    const float4* r  = (const float4*)(g_hs + (size_t)s * H);
    const float4* h4 = (const float4*)ht;
    float acc = 0.f;
#pragma unroll
    for (int i = 0; i < 8; i++) acc += dp4(r[lane + 32 * i], h4[lane + 32 * i]);
    acc = wred(acc);
    if (!lane) g_scores[s] = acc;
}

// ---------------- U precompute: blocks 0..127, warp holds Wtl_d row j in regs ----------------
__device__ __forceinline__ void u_precompute(const float* __restrict__ Wtl)
{
    const int b = blockIdx.x;
    if (b >= 128) return;
    const int w = threadIdx.x >> 5, lane = threadIdx.x & 31;
    const int j = b * NWARP + w;                     // 0..1023
    const float4* wr = (const float4*)(Wtl + (size_t)j * 2 * H);   // first half = d-part
    float4 wreg[8];
#pragma unroll
    for (int q = 0; q < 8; q++) wreg[q] = wr[lane + 32 * q];
    for (int s = 0; s < SLEN; s += 2) {
        const float4* h0 = (const float4*)(g_hs + (size_t)s * H);
        const float4* h1 = h0 + (H / 4);
        float a0 = 0.f, a1 = 0.f;
#pragma unroll
        for (int q = 0; q < 8; q++) {
            const int k = lane + 32 * q;
            a0 += dp4(wreg[q], h0[k]);
            a1 += dp4(wreg[q], h1[k]);
        }
        a0 = wred(a0);
        a1 = wred(a1);
        if (!lane) {
            g_U[(size_t)j * SLEN + s]     = a0;
            g_U[(size_t)j * SLEN + s + 1] = a1;
        }
    }
}

// ---------------- combine: softmax + ht2[j] = tanh(inv*Sum a~_s U[j,s] + V_j.ht + b_j) -----------
// blocks 256..511; warps 0..3 each own one column j.
__device__ __forceinline__ void combine_piece(const float* __restrict__ Wtl,
                                              const float* __restrict__ btl,
                                              const float* __restrict__ ht,
                                              float* s_sc, float* s_a, float* s_scalar)
{
    const int b = blockIdx.x;
    if (b < COMB0) return;
    const int tid = threadIdx.x, w = tid >> 5, lane = tid & 31;
    if (tid < SLEN) s_sc[tid] = g_scores[tid];
    __syncthreads();
    if (w == 0) {
        float m = -INFINITY;
#pragma unroll
        for (int q = 0; q < 4; q++) m = fmaxf(m, s_sc[lane + 32 * q]);
#pragma unroll
        for (int o = 16; o; o >>= 1) m = fmaxf(m, __shfl_xor_sync(0xffffffffu, m, o));
        float sum = 0.f;
#pragma unroll
        for (int q = 0; q < 4; q++) {
            float e = expf(s_sc[lane + 32 * q] - m);
            s_a[lane + 32 * q] = e;
            sum += e;
        }
#pragma unroll
        for (int o = 16; o; o >>= 1) sum += __shfl_xor_sync(0xffffffffu, sum, o);
        if (!lane) s_scalar[0] = 1.f / sum;
    }
    __syncthreads();
    if (w < 4) {
        const int j = (b - COMB0) * 4 + w;           // 0..1023
        const float4* vr = (const float4*)(Wtl + (size_t)j * 2 * H + H);  // second half
        const float4* h4 = (const float4*)ht;
        float acc = 0.f;
#pragma unroll
        for (int i = 0; i < 8; i++) acc += dp4(vr[lane + 32 * i], h4[lane + 32 * i]);
        // U term: lane covers 4 source positions
        float4 u = ((const float4*)(g_U + (size_t)j * SLEN))[lane];
        float au = u.x * s_a[lane * 4] + u.y * s_a[lane * 4 + 1]
                 + u.z * s_a[lane * 4 + 2] + u.w * s_a[lane * 4 + 3];
        float tot = wred(au * s_scalar[0] + acc);
        if (!lane) g_ht2[j] = tanhf(tot + btl[j]);
    }
}

// ---------------- logits GEMV (champion mapping + 2-row interleave) ----------------
__device__ __forceinline__ void logits_piece(const float* __restrict__ W,
                                             const float* __restrict__ bias,
                                             const float* __restrict__ vec,
                                             float* __restrict__ out_logits,
                                             float* s_v, int* s_i)
{
    const int tid = threadIdx.x, w = tid >> 5, lane = tid & 31;
    const float4* x4 = (const float4*)vec;
    float4 v[8];
#pragma unroll
    for (int q = 0; q < 8; q++) v[q] = x4[lane + 32 * q];
    const int gw = blockIdx.x * NWARP + w;           // 0..4095
    float best = -INFINITY; int bidx = VOCAB;
#pragma unroll
    for (int p = 0; p < 4; p++) {
        const int r0 = gw + 8192 * p;
        const int r1 = r0 + 4096;
        const float4* w0 = (const float4*)(W + (size_t)r0 * H);
        if (r1 < VOCAB) {
            const float4* w1 = (const float4*)(W + (size_t)r1 * H);
            float acc0 = 0.f, acc1 = 0.f;
#pragma unroll
            for (int q = 0; q < 8; q++) {
                const int k = lane + 32 * q;
                float4 a = __ldcs(w0 + k);
                float4 bb = __ldcs(w1 + k);
                acc0 += dp4(a, v[q]);
                acc1 += dp4(bb, v[q]);
            }
            acc0 = wred(acc0);
            acc1 = wred(acc1);
            if (!lane) {
                float l0 = acc0 + bias[r0];
                float l1 = acc1 + bias[r1];
                if (out_logits) { __stcs(out_logits + r0, l0); __stcs(out_logits + r1, l1); }
                if (l0 > best) { best = l0; bidx = r0; }
                if (l1 > best) { best = l1; bidx = r1; }
            }
        } else {
            float acc0 = 0.f;
#pragma unroll
            for (int q = 0; q < 8; q++) acc0 += dp4(__ldcs(w0 + lane + 32 * q), v[q]);
            acc0 = wred(acc0);
            if (!lane) {
                float l0 = acc0 + bias[r0];
                if (out_logits) __stcs(out_logits + r0, l0);
                if (l0 > best) { best = l0; bidx = r0; }
            }
        }
    }
    if (!lane) { s_v[w] = best; s_i[w] = bidx; }
    __syncthreads();
    if (tid == 0) {
        float bv = s_v[0]; int bi = s_i[0];
#pragma unroll
        for (int q = 1; q < NWARP; q++)
            if (s_v[q] > bv || (s_v[q] == bv && s_i[q] < bi)) { bv = s_v[q]; bi = s_i[q]; }
        g_pval[blockIdx.x] = bv; g_pidx[blockIdx.x] = bi;
    }
}

// ---------------- replicated finalize: EVERY block computes wid/done locally ----------------
__device__ __forceinline__ void finalize_repl(int step, int& wid, int& done,
                                              float* __restrict__ out_toks,
                                              float* s_v, int* s_i)
{
    const int t = threadIdx.x;
    float bv = g_pval[t];       int bi = g_pidx[t];
    float v2 = g_pval[t + 256]; int i2 = g_pidx[t + 256];
    if (v2 > bv || (v2 == bv && i2 < bi)) { bv = v2; bi = i2; }
    s_v[t] = bv; s_i[t] = bi;
    __syncthreads();
    for (int st = 128; st > 0; st >>= 1) {
        if (t < st) {
            float v = s_v[t + st]; int i = s_i[t + st];
            if (v > s_v[t] || (v == s_v[t] && i < s_i[t])) { s_v[t] = v; s_i[t] = i; }
        }
        __syncthreads();
    }
    const int wn = s_i[0];
    const int is_eos = (wn == EOS_ID);
    if (step >= 0 && blockIdx.x == 4 && t == 0)
        out_toks[step] = (float)((done || is_eos) ? -1 : wn);
    wid = wn;
    done = done | is_eos;
    __syncthreads();
}

// ---------------- the whole model, one persistent kernel ----------------
__global__ void __launch_bounds__(TPB, 4) k_main(
    const int* __restrict__ src,
    const float* __restrict__ embI,
    const float* __restrict__ WihE, const float* __restrict__ WhhE,
    const float* __restrict__ bihE, const float* __restrict__ bhhE,
    const float* __restrict__ Wli,  const float* __restrict__ bli,
    const float* __restrict__ embT,
    const float* __restrict__ WihD, const float* __restrict__ WhhD,
    const float* __restrict__ bihD, const float* __restrict__ bhhD,
    const float* __restrict__ Wlt,  const float* __restrict__ blt,
    const float* __restrict__ Wtl,  const float* __restrict__ btl,
    float* __restrict__ out)
{
    __shared__ float s_g[8];
    __shared__ float s_v[256];
    __shared__ int   s_i[256];
    __shared__ float s_sc[SLEN];
    __shared__ float s_a[SLEN];
    __shared__ float s_scalar[1];

    unsigned int gen = 0;
    float* out_logits = out + STEPS;
    const int b = blockIdx.x;
    const int w = threadIdx.x >> 5, lane = threadIdx.x & 31;
    int wid = 0, done = 0;           // replicated decode state (identical across all threads)

    // ---- P0: precompute Wih_e @ x_t for all 128 tokens; warp owns Wih row r = b*8+w ----
    {
        const int r = b * NWARP + w;
        const float4* wr = (const float4*)(WihE + (size_t)r * H);
        float4 wreg[8];
#pragma unroll
        for (int q = 0; q < 8; q++) wreg[q] = wr[lane + 32 * q];
        for (int t = 0; t < SLEN; t += 2) {
            const float4* x0 = (const float4*)(embI + (size_t)src[t]     * H);
            const float4* x1 = (const float4*)(embI + (size_t)src[t + 1] * H);
            float a0 = 0.f, a1 = 0.f;
#pragma unroll
            for (int q = 0; q < 8; q++) {
                const int k = lane + 32 * q;
                a0 += dp4(wreg[q], x0[k]);
                a1 += dp4(wreg[q], x1[k]);
            }
            a0 = wred(a0);
            a1 = wred(a1);
            if (!lane) {
                g_gih[(size_t)t       * (4 * H) + r] = a0;
                g_gih[(size_t)(t + 1) * (4 * H) + r] = a1;
            }
        }
    }
    gbar(gen);

    // ---- encoder: 128 steps, Whh-only GEMV + precomputed Wih term ----
    for (int t = 0; t < SLEN; t++) {
        lstm_whh(WhhE, g_hbuf[t & 1], s_g);
        lstm_pointwise_pre(t, bihE, bhhE, g_hbuf[(t + 1) & 1], g_hs + (size_t)t * H, s_g);
        gbar(gen);
    }
    // final encoder h in g_hbuf[0], c in g_c

    // ---- E1: first-word logits ----
    logits_piece(Wli, bli, g_hbuf[0], nullptr, s_v, s_i);
    gbar(gen);

    // ---- E2: replicated finalize -> wid0; initial decoder LSTM -> ht(0); U precompute ----
    finalize_repl(-1, wid, done, out, s_v, s_i);
    lstm_full(WihD, WhhD, bihD, bhhD, embT + (size_t)wid * H,
              g_hbuf[0], g_hbuf[1], nullptr, s_g);
    u_precompute(Wtl);
    gbar(gen);

    // ---- E3: scores(0) ----
    scores_piece(g_hbuf[1]);
    gbar(gen);

    // ---- decode loop: 2 grid barriers per step ----
    int cur = 1;                                    // ht(t) = g_hbuf[cur]
    for (int t = 0; t < STEPS; t++) {
        const float* ht  = g_hbuf[cur];
        float*       htn = g_hbuf[1 - cur];

        // Phase A: finalize(t-1) replicated; full LSTM -> ht(t+1); combine -> ht2(t) (blocks 256+)
        if (t > 0) finalize_repl(t - 1, wid, done, out, s_v, s_i);
        lstm_full(WihD, WhhD, bihD, bhhD, embT + (size_t)wid * H, ht, htn, nullptr, s_g);
        combine_piece(Wtl, btl, ht, s_sc, s_a, s_scalar);
        gbar(gen);

        // Phase B: logits(t) from ht2 (all blocks) || scores(t+1) (blocks 496..511)
        scores_piece(htn);
        logits_piece(Wlt, blt, g_ht2, out_logits + (size_t)t * VOCAB, s_v, s_i);
        gbar(gen);

        cur ^= 1;
    }
    finalize_repl(STEPS - 1, wid, done, out, s_v, s_i);
}

// ---------------- host orchestration ----------------
extern "C" void kernel_launch(void* const* d_in, const int* in_sizes, int n_in,
                              void* d_out, int out_size)
{
    const int*   src  = (const int*)  d_in[0];
    const float* embI = (const float*)d_in[1];
    const float* WihE = (const float*)d_in[2];
    const float* WhhE = (const float*)d_in[3];
    const float* bihE = (const float*)d_in[4];
    const float* bhhE = (const float*)d_in[5];
    const float* Wli  = (const float*)d_in[6];
    const float* bli  = (const float*)d_in[7];
    const float* embT = (const float*)d_in[8];
    const float* WihD = (const float*)d_in[9];
    const float* WhhD = (const float*)d_in[10];
    const float* bihD = (const float*)d_in[11];
    const float* bhhD = (const float*)d_in[12];
    const float* Wlt  = (const float*)d_in[13];
    const float* blt  = (const float*)d_in[14];
    const float* Wtl  = (const float*)d_in[15];
    const float* btl  = (const float*)d_in[16];

    k_init<<<1, 1024>>>();
    k_main<<<GRID, TPB>>>(src, embI, WihE, WhhE, bihE, bhhE, Wli, bli, embT,
                          WihD, WhhD, bihD, bhhD, Wlt, blt, Wtl, btl,
                          (float*)d_out);
}

// round 10
// speedup vs baseline: 1.3717x; 1.0021x over previous
#include <cuda_runtime.h>
#include <math.h>

#define H      1024
#define SLEN   128
#define VOCAB  32000
#define STEPS  51
#define EOS_ID 2
#define GRID   512
#define TPB    256
#define NWARP  8
#define COMB0  256                   // blocks [256..511] compute ht2 columns in phase A
#define WCACHE_BYTES (NWARP * H * 4) // 8 gate rows x 4KB = 32KB dynamic smem

// ---------------- persistent device state ----------------
__device__ float g_hbuf[2][H];
__device__ float g_c[H];
__device__ float g_hs[SLEN * H];
__device__ float g_gih[SLEN * 4 * H];   // precomputed Wih_e @ x_t
__device__ float g_U[H * SLEN];         // U[j][s] = Wtl_d[j] . hs[s]
__device__ float g_scores[SLEN];
__device__ float g_ht2[H];
__device__ float g_pval[GRID];
__device__ int   g_pidx[GRID];
__device__ unsigned int g_bar_count;

__global__ void k_init() {
    int t = threadIdx.x;             // 1024 threads
    g_hbuf[0][t] = 0.f;
    g_c[t] = 0.f;
    if (t == 0) g_bar_count = 0u;
}

// ---------------- grid barrier ----------------
__device__ __forceinline__ void gbar(unsigned int& gen) {
    __syncthreads();
    gen += GRID;
    if (threadIdx.x == 0) {
        asm volatile("fence.acq_rel.gpu;" ::: "memory");
        unsigned int prev = atomicAdd(&g_bar_count, 1u);
        if (prev + 1u != gen) {
            while (*(volatile unsigned int*)&g_bar_count < gen) { }
        }
        asm volatile("fence.acq_rel.gpu;" ::: "memory");
    }
    __syncthreads();
}

__device__ __forceinline__ float sigf(float x) { return 1.f / (1.f + expf(-x)); }
__device__ __forceinline__ float dp4(float4 a, float4 b) {
    return a.x * b.x + a.y * b.y + a.z * b.z + a.w * b.w;
}
__device__ __forceinline__ float wred(float v) {
#pragma unroll
    for (int o = 16; o; o >>= 1) v += __shfl_down_sync(0xffffffffu, v, o);
    return v;
}

// ---------------- Whh smem cache: warp w owns gate row (g*H + j), j = b*2 + w/4, g = w%4 ----------
__device__ __forceinline__ void stage_whh(const float* __restrict__ Whh, float4* s_w)
{
    const int b = blockIdx.x, w = threadIdx.x >> 5, lane = threadIdx.x & 31;
    const int j = b * 2 + (w >> 2), g = w & 3;
    const float4* src = (const float4*)(Whh + (size_t)(g * H + j) * H);
#pragma unroll
    for (int i = 0; i < 8; i++) s_w[w * 256 + lane + 32 * i] = src[lane + 32 * i];
}

// Whh half from the smem cache
__device__ __forceinline__ void lstm_whh_sm(const float4* s_w,
                                            const float* __restrict__ hprev, float* s_g)
{
    const int w = threadIdx.x >> 5, lane = threadIdx.x & 31;
    const float4* h4 = (const float4*)hprev;
    float acc = 0.f;
#pragma unroll
    for (int i = 0; i < 8; i++) acc += dp4(s_w[w * 256 + lane + 32 * i], h4[lane + 32 * i]);
    acc = wred(acc);
    if (!lane) s_g[w] = acc;
}

__device__ __forceinline__ void lstm_pointwise(const float* __restrict__ bih,
                                               const float* __restrict__ bhh,
                                               float* __restrict__ hnext,
                                               float* __restrict__ hs_out, float* s_g)
{
    __syncthreads();
    const int tid = threadIdx.x;
    if (tid < 2) {
        const int j = blockIdx.x * 2 + tid;
        const int base = tid * 4;
        float gi = s_g[base + 0] + bih[j]         + bhh[j];
        float gf = s_g[base + 1] + bih[H + j]     + bhh[H + j];
        float gg = s_g[base + 2] + bih[2 * H + j] + bhh[2 * H + j];
        float go = s_g[base + 3] + bih[3 * H + j] + bhh[3 * H + j];
        float i_ = sigf(gi), f_ = sigf(gf), g_ = tanhf(gg), o_ = sigf(go);
        float c2 = f_ * g_c[j] + i_ * g_;
        g_c[j] = c2;
        float hn = o_ * tanhf(c2);
        hnext[j] = hn;
        if (hs_out) hs_out[j] = hn;
    }
}

// encoder pointwise: adds precomputed Wih@x term from g_gih[t]
__device__ __forceinline__ void lstm_pointwise_pre(int t,
                                                   const float* __restrict__ bih,
                                                   const float* __restrict__ bhh,
                                                   float* __restrict__ hnext,
                                                   float* __restrict__ hs_out, float* s_g)
{
    __syncthreads();
    const int tid = threadIdx.x;
    if (tid < 2) {
        const int j = blockIdx.x * 2 + tid;
        const int base = tid * 4;
        const float* pre = g_gih + (size_t)t * (4 * H);
        float gi = s_g[base + 0] + pre[j]         + bih[j]         + bhh[j];
        float gf = s_g[base + 1] + pre[H + j]     + bih[H + j]     + bhh[H + j];
        float gg = s_g[base + 2] + pre[2 * H + j] + bih[2 * H + j] + bhh[2 * H + j];
        float go = s_g[base + 3] + pre[3 * H + j] + bih[3 * H + j] + bhh[3 * H + j];
        float i_ = sigf(gi), f_ = sigf(gf), g_ = tanhf(gg), o_ = sigf(go);
        float c2 = f_ * g_c[j] + i_ * g_;
        g_c[j] = c2;
        float hn = o_ * tanhf(c2);
        hnext[j] = hn;
        if (hs_out) hs_out[j] = hn;
    }
}

// full LSTM cell: Wih from global, Whh from the smem cache, same accumulation order as before
__device__ __forceinline__ void lstm_full_sm(const float* __restrict__ Wih,
                                             const float4* s_w,
                                             const float* __restrict__ bih,
                                             const float* __restrict__ bhh,
                                             const float* __restrict__ xrow,
                                             const float* __restrict__ hprev,
                                             float* __restrict__ hnext,
                                             float* __restrict__ hs_out, float* s_g)
{
    const int b = blockIdx.x, w = threadIdx.x >> 5, lane = threadIdx.x & 31;
    const int j = b * 2 + (w >> 2), g = w & 3;
    const float4* wi = (const float4*)(Wih + (size_t)(g * H + j) * H);
    const float4* x4 = (const float4*)xrow;
    const float4* h4 = (const float4*)hprev;
    float acc = 0.f;
#pragma unroll
    for (int i = 0; i < 8; i++) acc += dp4(wi[lane + 32 * i], x4[lane + 32 * i]);
#pragma unroll
    for (int i = 0; i < 8; i++) acc += dp4(s_w[w * 256 + lane + 32 * i], h4[lane + 32 * i]);
    acc = wred(acc);
    if (!lane) s_g[w] = acc;
    lstm_pointwise(bih, bhh, hnext, hs_out, s_g);
}

// ---------------- attention scores: blocks 496..511, one warp per source row ----------------
__device__ __forceinline__ void scores_piece(const float* __restrict__ ht)
{
    const int b = blockIdx.x;
    if (b < GRID - 16) return;
    const int w = threadIdx.x >> 5, lane = threadIdx.x & 31;
    const int s = (b - (GRID - 16)) * NWARP + w;     // 0..127
    const float4* r  = (const float4*)(g_hs + (size_t)s * H);
    const float4* h4 = (const float4*)ht;
    float acc = 0.f;
#pragma unroll
    for (int i = 0; i < 8; i++) acc += dp4(r[lane + 32 * i], h4[lane + 32 * i]);
    acc = wred(acc);
    if (!lane) g_scores[s] = acc;
}

// ---------------- U precompute: blocks 0..127, warp holds Wtl_d row j in regs ----------------
__device__ __forceinline__ void u_precompute(const float* __restrict__ Wtl)
{
    const int b = blockIdx.x;
    if (b >= 128) return;
    const int w = threadIdx.x >> 5, lane = threadIdx.x & 31;
    const int j = b * NWARP + w;                     // 0..1023
    const float4* wr = (const float4*)(Wtl + (size_t)j * 2 * H);   // first half = d-part
    float4 wreg[8];
#pragma unroll
    for (int q = 0; q < 8; q++) wreg[q] = wr[lane + 32 * q];
    for (int s = 0; s < SLEN; s += 2) {
        const float4* h0 = (const float4*)(g_hs + (size_t)s * H);
        const float4* h1 = h0 + (H / 4);
        float a0 = 0.f, a1 = 0.f;
#pragma unroll
        for (int q = 0; q < 8; q++) {
            const int k = lane + 32 * q;
            a0 += dp4(wreg[q], h0[k]);
            a1 += dp4(wreg[q], h1[k]);
        }
        a0 = wred(a0);
        a1 = wred(a1);
        if (!lane) {
            g_U[(size_t)j * SLEN + s]     = a0;
            g_U[(size_t)j * SLEN + s + 1] = a1;
        }
    }
}

// ---------------- combine: softmax + ht2[j] = tanh(inv*Sum a~_s U[j,s] + V_j.ht + b_j) -----------
__device__ __forceinline__ void combine_piece(const float* __restrict__ Wtl,
                                              const float* __restrict__ btl,
                                              const float* __restrict__ ht,
                                              float* s_sc, float* s_a, float* s_scalar)
{
    const int b = blockIdx.x;
    if (b < COMB0) return;
    const int tid = threadIdx.x, w = tid >> 5, lane = tid & 31;
    if (tid < SLEN) s_sc[tid] = g_scores[tid];
    __syncthreads();
    if (w == 0) {
        float m = -INFINITY;
#pragma unroll
        for (int q = 0; q < 4; q++) m = fmaxf(m, s_sc[lane + 32 * q]);
#pragma unroll
        for (int o = 16; o; o >>= 1) m = fmaxf(m, __shfl_xor_sync(0xffffffffu, m, o));
        float sum = 0.f;
#pragma unroll
        for (int q = 0; q < 4; q++) {
            float e = expf(s_sc[lane + 32 * q] - m);
            s_a[lane + 32 * q] = e;
            sum += e;
        }
#pragma unroll
        for (int o = 16; o; o >>= 1) sum += __shfl_xor_sync(0xffffffffu, sum, o);
        if (!lane) s_scalar[0] = 1.f / sum;
    }
    __syncthreads();
    if (w < 4) {
        const int j = (b - COMB0) * 4 + w;           // 0..1023
        const float4* vr = (const float4*)(Wtl + (size_t)j * 2 * H + H);  // second half
        const float4* h4 = (const float4*)ht;
        float acc = 0.f;
#pragma unroll
        for (int i = 0; i < 8; i++) acc += dp4(vr[lane + 32 * i], h4[lane + 32 * i]);
        float4 u = ((const float4*)(g_U + (size_t)j * SLEN))[lane];
        float au = u.x * s_a[lane * 4] + u.y * s_a[lane * 4 + 1]
                 + u.z * s_a[lane * 4 + 2] + u.w * s_a[lane * 4 + 3];
        float tot = wred(au * s_scalar[0] + acc);
        if (!lane) g_ht2[j] = tanhf(tot + btl[j]);
    }
}

// ---------------- logits GEMV (champion mapping + 2-row interleave) ----------------
__device__ __forceinline__ void logits_piece(const float* __restrict__ W,
                                             const float* __restrict__ bias,
                                             const float* __restrict__ vec,
                                             float* __restrict__ out_logits,
                                             float* s_v, int* s_i)
{
    const int tid = threadIdx.x, w = tid >> 5, lane = tid & 31;
    const float4* x4 = (const float4*)vec;
    float4 v[8];
#pragma unroll
    for (int q = 0; q < 8; q++) v[q] = x4[lane + 32 * q];
    const int gw = blockIdx.x * NWARP + w;           // 0..4095
    float best = -INFINITY; int bidx = VOCAB;
#pragma unroll
    for (int p = 0; p < 4; p++) {
        const int r0 = gw + 8192 * p;
        const int r1 = r0 + 4096;
        const float4* w0 = (const float4*)(W + (size_t)r0 * H);
        if (r1 < VOCAB) {
            const float4* w1 = (const float4*)(W + (size_t)r1 * H);
            float acc0 = 0.f, acc1 = 0.f;
#pragma unroll
            for (int q = 0; q < 8; q++) {
                const int k = lane + 32 * q;
                float4 a = __ldcs(w0 + k);
                float4 bb = __ldcs(w1 + k);
                acc0 += dp4(a, v[q]);
                acc1 += dp4(bb, v[q]);
            }
            acc0 = wred(acc0);
            acc1 = wred(acc1);
            if (!lane) {
                float l0 = acc0 + bias[r0];
                float l1 = acc1 + bias[r1];
                if (out_logits) { __stcs(out_logits + r0, l0); __stcs(out_logits + r1, l1); }
                if (l0 > best) { best = l0; bidx = r0; }
                if (l1 > best) { best = l1; bidx = r1; }
            }
        } else {
            float acc0 = 0.f;
#pragma unroll
            for (int q = 0; q < 8; q++) acc0 += dp4(__ldcs(w0 + lane + 32 * q), v[q]);
            acc0 = wred(acc0);
            if (!lane) {
                float l0 = acc0 + bias[r0];
                if (out_logits) __stcs(out_logits + r0, l0);
                if (l0 > best) { best = l0; bidx = r0; }
            }
        }
    }
    if (!lane) { s_v[w] = best; s_i[w] = bidx; }
    __syncthreads();
    if (tid == 0) {
        float bv = s_v[0]; int bi = s_i[0];
#pragma unroll
        for (int q = 1; q < NWARP; q++)
            if (s_v[q] > bv || (s_v[q] == bv && s_i[q] < bi)) { bv = s_v[q]; bi = s_i[q]; }
        g_pval[blockIdx.x] = bv; g_pidx[blockIdx.x] = bi;
    }
}

// ---------------- replicated finalize: EVERY block computes wid/done locally ----------------
__device__ __forceinline__ void finalize_repl(int step, int& wid, int& done,
                                              float* __restrict__ out_toks,
                                              float* s_v, int* s_i)
{
    const int t = threadIdx.x;
    float bv = g_pval[t];       int bi = g_pidx[t];
    float v2 = g_pval[t + 256]; int i2 = g_pidx[t + 256];
    if (v2 > bv || (v2 == bv && i2 < bi)) { bv = v2; bi = i2; }
    s_v[t] = bv; s_i[t] = bi;
    __syncthreads();
    for (int st = 128; st > 0; st >>= 1) {
        if (t < st) {
            float v = s_v[t + st]; int i = s_i[t + st];
            if (v > s_v[t] || (v == s_v[t] && i < s_i[t])) { s_v[t] = v; s_i[t] = i; }
        }
        __syncthreads();
    }
    const int wn = s_i[0];
    const int is_eos = (wn == EOS_ID);
    if (step >= 0 && blockIdx.x == 4 && t == 0)
        out_toks[step] = (float)((done || is_eos) ? -1 : wn);
    wid = wn;
    done = done | is_eos;
    __syncthreads();
}

// ---------------- the whole model, one persistent kernel ----------------
__global__ void __launch_bounds__(TPB, 4) k_main(
    const int* __restrict__ src,
    const float* __restrict__ embI,
    const float* __restrict__ WihE, const float* __restrict__ WhhE,
    const float* __restrict__ bihE, const float* __restrict__ bhhE,
    const float* __restrict__ Wli,  const float* __restrict__ bli,
    const float* __restrict__ embT,
    const float* __restrict__ WihD, const float* __restrict__ WhhD,
    const float* __restrict__ bihD, const float* __restrict__ bhhD,
    const float* __restrict__ Wlt,  const float* __restrict__ blt,
    const float* __restrict__ Wtl,  const float* __restrict__ btl,
    float* __restrict__ out)
{
    extern __shared__ float4 s_w[];  // 2048 float4 = 32KB Whh row cache (per-block rows)
    __shared__ float s_g[8];
    __shared__ float s_v[256];
    __shared__ int   s_i[256];
    __shared__ float s_sc[SLEN];
    __shared__ float s_a[SLEN];
    __shared__ float s_scalar[1];

    unsigned int gen = 0;
    float* out_logits = out + STEPS;
    const int b = blockIdx.x;
    const int w = threadIdx.x >> 5, lane = threadIdx.x & 31;
    int wid = 0, done = 0;

    // ---- P0: precompute Wih_e @ x_t for all 128 tokens + stage WhhE rows into smem ----
    stage_whh(WhhE, s_w);
    {
        const int r = b * NWARP + w;
        const float4* wr = (const float4*)(WihE + (size_t)r * H);
        float4 wreg[8];
#pragma unroll
        for (int q = 0; q < 8; q++) wreg[q] = wr[lane + 32 * q];
        for (int t = 0; t < SLEN; t += 2) {
            const float4* x0 = (const float4*)(embI + (size_t)src[t]     * H);
            const float4* x1 = (const float4*)(embI + (size_t)src[t + 1] * H);
            float a0 = 0.f, a1 = 0.f;
#pragma unroll
            for (int q = 0; q < 8; q++) {
                const int k = lane + 32 * q;
                a0 += dp4(wreg[q], x0[k]);
                a1 += dp4(wreg[q], x1[k]);
            }
            a0 = wred(a0);
            a1 = wred(a1);
            if (!lane) {
                g_gih[(size_t)t       * (4 * H) + r] = a0;
                g_gih[(size_t)(t + 1) * (4 * H) + r] = a1;
            }
        }
    }
    gbar(gen);

    // ---- encoder: 128 steps, Whh GEMV from SMEM + precomputed Wih term ----
    for (int t = 0; t < SLEN; t++) {
        lstm_whh_sm(s_w, g_hbuf[t & 1], s_g);
        lstm_pointwise_pre(t, bihE, bhhE, g_hbuf[(t + 1) & 1], g_hs + (size_t)t * H, s_g);
        gbar(gen);
    }
    // final encoder h in g_hbuf[0], c in g_c

    // ---- E1: first-word logits; re-stage the cache with WhhD for the decoder ----
    logits_piece(Wli, bli, g_hbuf[0], nullptr, s_v, s_i);
    __syncthreads();                  // all logits reads of s_v/s_i done before restage write? (s_w disjoint; sync for phase hygiene)
    stage_whh(WhhD, s_w);
    gbar(gen);

    // ---- E2: replicated finalize -> wid0; initial decoder LSTM -> ht(0); U precompute ----
    finalize_repl(-1, wid, done, out, s_v, s_i);
    lstm_full_sm(WihD, s_w, bihD, bhhD, embT + (size_t)wid * H,
                 g_hbuf[0], g_hbuf[1], nullptr, s_g);
    u_precompute(Wtl);
    gbar(gen);

    // ---- E3: scores(0) ----
    scores_piece(g_hbuf[1]);
    gbar(gen);

    // ---- decode loop: 2 grid barriers per step ----
    int cur = 1;                                    // ht(t) = g_hbuf[cur]
    for (int t = 0; t < STEPS; t++) {
        const float* ht  = g_hbuf[cur];
        float*       htn = g_hbuf[1 - cur];

        // Phase A: finalize(t-1) replicated; full LSTM (Whh from smem) -> ht(t+1); combine -> ht2(t)
        if (t > 0) finalize_repl(t - 1, wid, done, out, s_v, s_i);
        lstm_full_sm(WihD, s_w, bihD, bhhD, embT + (size_t)wid * H, ht, htn, nullptr, s_g);
        combine_piece(Wtl, btl, ht, s_sc, s_a, s_scalar);
        gbar(gen);

        // Phase B: logits(t) from ht2 (all blocks) || scores(t+1) (blocks 496..511)
        scores_piece(htn);
        logits_piece(Wlt, blt, g_ht2, out_logits + (size_t)t * VOCAB, s_v, s_i);
        gbar(gen);

        cur ^= 1;
    }
    finalize_repl(STEPS - 1, wid, done, out, s_v, s_i);
}

// ---------------- host orchestration ----------------
extern "C" void kernel_launch(void* const* d_in, const int* in_sizes, int n_in,
                              void* d_out, int out_size)
{
    const int*   src  = (const int*)  d_in[0];
    const float* embI = (const float*)d_in[1];
    const float* WihE = (const float*)d_in[2];
    const float* WhhE = (const float*)d_in[3];
    const float* bihE = (const float*)d_in[4];
    const float* bhhE = (const float*)d_in[5];
    const float* Wli  = (const float*)d_in[6];
    const float* bli  = (const float*)d_in[7];
    const float* embT = (const float*)d_in[8];
    const float* WihD = (const float*)d_in[9];
    const float* WhhD = (const float*)d_in[10];
    const float* bihD = (const float*)d_in[11];
    const float* bhhD = (const float*)d_in[12];
    const float* Wlt  = (const float*)d_in[13];
    const float* blt  = (const float*)d_in[14];
    const float* Wtl  = (const float*)d_in[15];
    const float* btl  = (const float*)d_in[16];

    k_init<<<1, 1024>>>();
    k_main<<<GRID, TPB, WCACHE_BYTES>>>(src, embI, WihE, WhhE, bihE, bhhE, Wli, bli, embT,
                                        WihD, WhhD, bihD, bhhD, Wlt, blt, Wtl, btl,
                                        (float*)d_out);
}